// round 12
// baseline (speedup 1.0000x reference)
#include <cuda_runtime.h>
#include <cuda_bf16.h>
#include <cstdint>
#include <math.h>

#define B_    16
#define CDIM  128
#define LSEQ  9216
#define DSTATE 2
#define DTRANK 8
#define OUTC  128
#define NPROJ 12
#define SUB   64
#define NSUB  144          // LSEQ/64
#define NTILE 72           // LSEQ/128
#define LOG2E 1.4426950408889634f

// ---------------- device scratch ----------------
__device__ float g_zsilu[(size_t)B_*LSEQ*CDIM];
__device__ float g_xi   [(size_t)B_*LSEQ*CDIM];
__device__ float g_dt   [(size_t)B_*LSEQ*CDIM];
__device__ float g_bc   [(size_t)B_*LSEQ*4];
__device__ float g_aggA [(size_t)B_*NSUB*CDIM*DSTATE];
__device__ float g_aggH [(size_t)B_*NSUB*CDIM*DSTATE];
__device__ float g_hinit[(size_t)B_*NSUB*CDIM*DSTATE];

__device__ __forceinline__ float silu_f(float v) {
    return __fdividef(v, 1.0f + __expf(-v));
}
__device__ __forceinline__ uint32_t smem_u32(const void* p) {
    uint32_t a;
    asm("{ .reg .u64 t; cvta.to.shared.u64 t, %1; cvt.u32.u64 %0, t; }" : "=r"(a) : "l"(p));
    return a;
}

#define LDMX4(r0,r1,r2,r3,addr) \
    asm volatile("ldmatrix.sync.aligned.m8n8.x4.shared.b16 {%0,%1,%2,%3}, [%4];" \
        : "=r"(r0),"=r"(r1),"=r"(r2),"=r"(r3) : "r"(addr))
#define MMA_BF16(D, A, B) \
    asm volatile("mma.sync.aligned.m16n8k16.row.col.f32.bf16.bf16.f32 " \
        "{%0,%1,%2,%3}, {%4,%5,%6,%7}, {%8,%9}, {%0,%1,%2,%3};" \
        : "+f"((D)[0]), "+f"((D)[1]), "+f"((D)[2]), "+f"((D)[3]) \
        : "r"((A)[0]), "r"((A)[1]), "r"((A)[2]), "r"((A)[3]), "r"((B)[0]), "r"((B)[1]))

__device__ __forceinline__ void split_pack(float4 v, uint2& hi, uint2& lo) {
    __nv_bfloat162 h0 = __floats2bfloat162_rn(v.x, v.y);
    __nv_bfloat162 h1 = __floats2bfloat162_rn(v.z, v.w);
    float r0 = v.x - __bfloat162float(h0.x);
    float r1 = v.y - __bfloat162float(h0.y);
    float r2 = v.z - __bfloat162float(h1.x);
    float r3 = v.w - __bfloat162float(h1.y);
    __nv_bfloat162 l0 = __floats2bfloat162_rn(r0, r1);
    __nv_bfloat162 l1 = __floats2bfloat162_rn(r2, r3);
    hi = make_uint2(*reinterpret_cast<uint32_t*>(&h0), *reinterpret_cast<uint32_t*>(&h1));
    lo = make_uint2(*reinterpret_cast<uint32_t*>(&l0), *reinterpret_cast<uint32_t*>(&l1));
}

// bf16 operand tiles: [128 rows][128 k], pitch 272 B
#define TPITCH_B 272u
#define TILE_B   (128u*TPITCH_B)      // 34816
#define SM_BH    0u
#define SM_BL    34816u
#define SM_AH    69632u
#define SM_AL    104448u

// verified 128x128x128 3-term hi/lo MMA tile (8 warps, warp = 64m x 32n)
__device__ __forceinline__ void mma_tile(float (*d)[4][4], uint32_t sb,
        uint32_t oAH, uint32_t oAL, uint32_t oBH, uint32_t oBL,
        int lane, int wm, int wn) {
    const uint32_t a_off = (uint32_t)((lane & 15) * TPITCH_B + ((lane >> 4) * 8) * 2);
    const uint32_t b_off = (uint32_t)((((lane >> 4) & 1) * 8 + (lane & 7)) * TPITCH_B
                                      + (((lane >> 3) & 1) * 8) * 2);
#pragma unroll
    for (int i = 0; i < 4; i++)
#pragma unroll
        for (int j = 0; j < 4; j++)
#pragma unroll
            for (int q = 0; q < 4; q++) d[i][j][q] = 0.f;

#pragma unroll 1
    for (int ks = 0; ks < 8; ks++) {
        const uint32_t kb = ks * 32;
        uint32_t ah[4][4], al[4][4], bh[4][2], bl[4][2];
#pragma unroll
        for (int mf = 0; mf < 4; mf++) {
            uint32_t off = (wm*64 + mf*16) * TPITCH_B + kb + a_off;
            LDMX4(ah[mf][0], ah[mf][1], ah[mf][2], ah[mf][3], sb + oAH + off);
            LDMX4(al[mf][0], al[mf][1], al[mf][2], al[mf][3], sb + oAL + off);
        }
#pragma unroll
        for (int p = 0; p < 2; p++) {
            uint32_t off = (wn*32 + p*16) * TPITCH_B + kb + b_off;
            LDMX4(bh[2*p][0], bh[2*p][1], bh[2*p+1][0], bh[2*p+1][1], sb + oBH + off);
            LDMX4(bl[2*p][0], bl[2*p][1], bl[2*p+1][0], bl[2*p+1][1], sb + oBL + off);
        }
#pragma unroll
        for (int mf = 0; mf < 4; mf++)
#pragma unroll
            for (int nf = 0; nf < 4; nf++) {
                MMA_BF16(d[mf][nf], ah[mf], bh[nf]);
                MMA_BF16(d[mf][nf], ah[mf], bl[nf]);
                MMA_BF16(d[mf][nf], al[mf], bh[nf]);
            }
    }
}

// K1 smem overlays (beyond the 4 operand tiles)
#define K1_XI   69632u                  // f32 [128][132] xi tile (over AH/AL, post-MMA)
#define K1_XW   137216u                 // f32 [12][132] x_proj_w
#define K1_XD   143552u                 // f32 [128][16] x_dbl
#define K1_XH   151744u                 // f32 [3][128] halo x cols
#define K1_SMEM 153280u

// ---------------------------------------------------------------------------
// K1 mega: in_proj MMA (both halves) + silu(z) + conv + x_proj + dt + subchunk
// aggregates. Grid (NTILE, B_), 256 threads.
// ---------------------------------------------------------------------------
__global__ __launch_bounds__(256)
void k_mega1(const float* __restrict__ x, const float* __restrict__ Wi,
             const float* __restrict__ conv_w, const float* __restrict__ conv_b,
             const float* __restrict__ x_proj_w, const float* __restrict__ dt_proj_w,
             const float* __restrict__ dt_proj_b, const float* __restrict__ A_log) {
    extern __shared__ __align__(16) char smraw[];
    const uint32_t sb = smem_u32(smraw);
    const int tid  = threadIdx.x;
    const int lane = tid & 31;
    const int wid  = tid >> 5;
    const int wm   = wid >> 2;
    const int wn   = wid & 3;
    const int b    = blockIdx.y;
    const int l0   = blockIdx.x * 128;

    // --- B: x tile [k][l] -> [l][k] bf16 hi/lo ---
    {
        const float* xb = x + (size_t)b * CDIM * LSEQ;
        for (int idx = tid; idx < 128 * 32; idx += 256) {
            int k = idx >> 5, l4 = (idx & 31) * 4;
            float4 v = *reinterpret_cast<const float4*>(&xb[(size_t)k * LSEQ + l0 + l4]);
            float vv[4] = {v.x, v.y, v.z, v.w};
#pragma unroll
            for (int i = 0; i < 4; i++) {
                __nv_bfloat16 h = __float2bfloat16(vv[i]);
                __nv_bfloat16 l = __float2bfloat16(vv[i] - __bfloat162float(h));
                uint32_t off = (l4 + i) * TPITCH_B + k * 2;
                *reinterpret_cast<__nv_bfloat16*>(smraw + SM_BH + off) = h;
                *reinterpret_cast<__nv_bfloat16*>(smraw + SM_BL + off) = l;
            }
        }
    }
    // --- A: Wi z-half (rows 128..255) ---
    for (int idx = tid; idx < 128 * 32; idx += 256) {
        int e = idx >> 5, k4 = (idx & 31) * 4;
        float4 w = *reinterpret_cast<const float4*>(&Wi[(size_t)(128 + e) * CDIM + k4]);
        uint2 hi, lo; split_pack(w, hi, lo);
        uint32_t off = e * TPITCH_B + k4 * 2;
        *reinterpret_cast<uint2*>(smraw + SM_AH + off) = hi;
        *reinterpret_cast<uint2*>(smraw + SM_AL + off) = lo;
    }
    __syncthreads();

    float acc[4][4][4];
    mma_tile(acc, sb, SM_AH, SM_AL, SM_BH, SM_BL, lane, wm, wn);
    __syncthreads();

    // stage z [e][l] (pitch 129) over AH/AL region
    {
        float* ztile = reinterpret_cast<float*>(smraw + SM_AH);
#pragma unroll
        for (int mf = 0; mf < 4; mf++)
#pragma unroll
            for (int nf = 0; nf < 4; nf++) {
                int row = wm*64 + mf*16 + (lane >> 2);
                int col = wn*32 + nf*8 + (lane & 3) * 2;
                ztile[ row      * 129 + col    ] = acc[mf][nf][0];
                ztile[ row      * 129 + col + 1] = acc[mf][nf][1];
                ztile[(row + 8) * 129 + col    ] = acc[mf][nf][2];
                ztile[(row + 8) * 129 + col + 1] = acc[mf][nf][3];
            }
    }
    __syncthreads();
    {
        const float* ztile = reinterpret_cast<const float*>(smraw + SM_AH);
        for (int idx = tid; idx < 128 * 32; idx += 256) {
            int l = idx >> 5, e4 = (idx & 31) * 4;
            float4 v;
            v.x = silu_f(ztile[(e4+0)*129 + l]);
            v.y = silu_f(ztile[(e4+1)*129 + l]);
            v.z = silu_f(ztile[(e4+2)*129 + l]);
            v.w = silu_f(ztile[(e4+3)*129 + l]);
            *reinterpret_cast<float4*>(&g_zsilu[((size_t)b*LSEQ + l0 + l)*CDIM + e4]) = v;
        }
    }
    __syncthreads();

    // --- A: Wi x-half (rows 0..127) ---
    for (int idx = tid; idx < 128 * 32; idx += 256) {
        int e = idx >> 5, k4 = (idx & 31) * 4;
        float4 w = *reinterpret_cast<const float4*>(&Wi[(size_t)e * CDIM + k4]);
        uint2 hi, lo; split_pack(w, hi, lo);
        uint32_t off = e * TPITCH_B + k4 * 2;
        *reinterpret_cast<uint2*>(smraw + SM_AH + off) = hi;
        *reinterpret_cast<uint2*>(smraw + SM_AL + off) = lo;
    }
    __syncthreads();
    mma_tile(acc, sb, SM_AH, SM_AL, SM_BH, SM_BL, lane, wm, wn);
    __syncthreads();

    // stage xraw tile [row=3+l][d=e] pitch 132 at offset 0 (over BH/BL)
    float* xtile = reinterpret_cast<float*>(smraw);      // [131][132]
#pragma unroll
    for (int mf = 0; mf < 4; mf++)
#pragma unroll
        for (int nf = 0; nf < 4; nf++) {
            int e   = wm*64 + mf*16 + (lane >> 2);
            int col = wn*32 + nf*8 + (lane & 3) * 2;
            xtile[(3 + col    )*132 + e    ] = acc[mf][nf][0];
            xtile[(3 + col + 1)*132 + e    ] = acc[mf][nf][1];
            xtile[(3 + col    )*132 + e + 8] = acc[mf][nf][2];
            xtile[(3 + col + 1)*132 + e + 8] = acc[mf][nf][3];
        }
    // halo x cols (disjoint smem region, no sync needed vs staging above)
    {
        float* xh = reinterpret_cast<float*>(smraw + K1_XH);
        const float* xb = x + (size_t)b * CDIM * LSEQ;
        for (int i = tid; i < 3 * 128; i += 256) {
            int j = i >> 7, k = i & 127;
            int lh = l0 - 3 + j;
            xh[i] = (lh >= 0) ? xb[(size_t)k * LSEQ + lh] : 0.f;
        }
    }
    __syncthreads();
    {
        // halo GEMV -> xtile rows 0..2 directly; x_proj_w load in parallel
        const float* xh = reinterpret_cast<const float*>(smraw + K1_XH);
        for (int t = tid; t < 3 * 128; t += 256) {
            int j = t >> 7, d2 = t & 127;
            const float* wr = &Wi[(size_t)d2 * CDIM];
            const float* xr = &xh[j * 128];
            float s = 0.f;
#pragma unroll 8
            for (int k = 0; k < CDIM; k++) s = fmaf(wr[k], xr[k], s);
            xtile[j * 132 + d2] = s;
        }
        float* xw = reinterpret_cast<float*>(smraw + K1_XW);
        for (int i = tid; i < NPROJ*CDIM; i += 256)
            xw[(i >> 7)*132 + (i & 127)] = x_proj_w[i];
    }
    __syncthreads();

    // conv + silu: thread (d, half) over 64 tokens; xi tile at K1_XI, also g_xi
    const int d    = tid & 127;
    const int half = tid >> 7;
    float* xi_s = reinterpret_cast<float*>(smraw + K1_XI);   // [128][132]
    {
        const float cw0 = conv_w[d*4+0], cw1 = conv_w[d*4+1];
        const float cw2 = conv_w[d*4+2], cw3 = conv_w[d*4+3];
        const float cb  = conv_b[d];
        const int ls = half * 64;
        float* xo = g_xi + ((size_t)b * LSEQ + l0) * CDIM + d;
        float p0 = xtile[(ls  )*132 + d];
        float p1 = xtile[(ls+1)*132 + d];
        float p2 = xtile[(ls+2)*132 + d];
#pragma unroll 4
        for (int l = ls; l < ls + 64; l++) {
            float c = xtile[(l+3)*132 + d];
            float a = fmaf(cw0,p0, fmaf(cw1,p1, fmaf(cw2,p2, fmaf(cw3,c, cb))));
            float v = silu_f(a);
            xi_s[l*132 + d] = v;
            xo[(size_t)l*CDIM] = v;
            p0 = p1; p1 = p2; p2 = c;
        }
    }
    __syncthreads();

    // x_proj: 128 tokens x 12 dots
    {
        const float* xw = reinterpret_cast<const float*>(smraw + K1_XW);
        float* xd_s = reinterpret_cast<float*>(smraw + K1_XD);
        float* bco = g_bc + ((size_t)b * LSEQ + l0) * 4;
        for (int p = tid; p < 128*NPROJ; p += 256) {
            int l = p / 12, j = p - l*12;
            const float4* xr4 = reinterpret_cast<const float4*>(&xi_s[l*132]);
            const float4* wr4 = reinterpret_cast<const float4*>(&xw[j*132]);
            float s = 0.f;
#pragma unroll
            for (int k = 0; k < 32; k++) {
                float4 xa = xr4[k], wa = wr4[k];
                s = fmaf(xa.x, wa.x, s); s = fmaf(xa.y, wa.y, s);
                s = fmaf(xa.z, wa.z, s); s = fmaf(xa.w, wa.w, s);
            }
            xd_s[l*16 + j] = s;
            if (j >= 8) bco[l*4 + (j-8)] = s;
        }
    }
    __syncthreads();

    // dt + subchunk aggregates: thread (d, half) over 64 tokens
    {
        const float* xd_s = reinterpret_cast<const float*>(smraw + K1_XD);
        float wdt[DTRANK];
#pragma unroll
        for (int r = 0; r < DTRANK; r++) wdt[r] = dt_proj_w[d*DTRANK + r];
        const float bdt = dt_proj_b[d];
        const float a0L = -__expf(A_log[2*d+0]) * LOG2E;
        const float a1L = -__expf(A_log[2*d+1]) * LOG2E;
        const int ls = half * 64;
        float* dto = g_dt + ((size_t)b * LSEQ + l0 + ls) * CDIM + d;

        float h0 = 0.f, h1 = 0.f, sdt = 0.f;
#pragma unroll 2
        for (int i = 0; i < SUB; i++) {
            const float* xd = &xd_s[(ls + i)*16];
            float t = bdt;
#pragma unroll
            for (int r = 0; r < DTRANK; r++) t = fmaf(xd[r], wdt[r], t);
            float ex = __expf(t);
            float dt = (t > 20.f) ? t : __logf(1.f + ex);
            dto[(size_t)i*CDIM] = dt;
            sdt += dt;
            float e0 = exp2f(dt * a0L);
            float e1 = exp2f(dt * a1L);
            float dbx = dt * xi_s[(ls + i)*132 + d];
            h0 = fmaf(e0, h0, dbx * xd[8]);
            h1 = fmaf(e1, h1, dbx * xd[9]);
        }
        const int sub = blockIdx.x * 2 + half;
        const size_t base = (((size_t)b*NSUB + sub)*CDIM + d)*DSTATE;
        g_aggA[base+0] = exp2f(a0L * sdt);
        g_aggA[base+1] = exp2f(a1L * sdt);
        g_aggH[base+0] = h0;
        g_aggH[base+1] = h1;
    }
}

// ---------------------------------------------------------------------------
// K2: chain subchunk aggregates (4096 chains, len 144)
// ---------------------------------------------------------------------------
__global__ __launch_bounds__(256)
void k_combine() {
    const int g = blockIdx.x * blockDim.x + threadIdx.x;
    const int b = g >> 8;
    const int rem = g & 255;
    float h = 0.f;
    for (int s = 0; s < NSUB; s++) {
        const size_t idx = (((size_t)b*NSUB + s) * CDIM * DSTATE) + rem;
        g_hinit[idx] = h;
        h = fmaf(g_aggA[idx], h, g_aggH[idx]);
    }
}

// ---------------------------------------------------------------------------
// K3 mega: scan -> y (bf16 hi/lo, direct to MMA operand) + out_proj MMA + LN.
// Grid (NTILE, B_), 256 threads.
// ---------------------------------------------------------------------------
#define K3_BC   139264u
#define K3_SMEM 141312u

__global__ __launch_bounds__(256)
void k_mega2(const float* __restrict__ Wout, const float* __restrict__ gamma,
             const float* __restrict__ beta, const float* __restrict__ A_log,
             const float* __restrict__ D_param, float* __restrict__ out) {
    extern __shared__ __align__(16) char smraw[];
    const uint32_t sb = smem_u32(smraw);
    const int tid  = threadIdx.x;
    const int lane = tid & 31;
    const int wid  = tid >> 5;
    const int wm   = wid >> 2;
    const int wn   = wid & 3;
    const int b    = blockIdx.y;
    const int l0   = blockIdx.x * 128;

    // Wout -> AH/AL
    for (int idx = tid; idx < 128 * 32; idx += 256) {
        int o = idx >> 5, k4 = (idx & 31) * 4;
        float4 w = *reinterpret_cast<const float4*>(&Wout[(size_t)o * CDIM + k4]);
        uint2 hi, lo; split_pack(w, hi, lo);
        uint32_t off = o * TPITCH_B + k4 * 2;
        *reinterpret_cast<uint2*>(smraw + SM_AH + off) = hi;
        *reinterpret_cast<uint2*>(smraw + SM_AL + off) = lo;
    }
    // bc
    {
        float4* bc4 = reinterpret_cast<float4*>(smraw + K3_BC);
        const float4* bcg = reinterpret_cast<const float4*>(g_bc + ((size_t)b*LSEQ + l0)*4);
        for (int i = tid; i < 128; i += 256) bc4[i] = bcg[i];
    }
    __syncthreads();

    // scan: thread (d, half) over its 64-token subchunk, write y -> BH/BL
    {
        const int d    = tid & 127;
        const int half = tid >> 7;
        const int sub  = blockIdx.x * 2 + half;
        const int ls   = half * 64;
        const float* bc_s = reinterpret_cast<const float*>(smraw + K3_BC);
        const float a0L = -__expf(A_log[2*d+0]) * LOG2E;
        const float a1L = -__expf(A_log[2*d+1]) * LOG2E;
        const float Dp  = D_param[d];
        const size_t hb = (((size_t)b*NSUB + sub)*CDIM + d)*DSTATE;
        float h0 = g_hinit[hb+0];
        float h1 = g_hinit[hb+1];
        const size_t off = ((size_t)b * LSEQ + l0 + ls) * CDIM + d;
        const float* dtp = g_dt    + off;
        const float* xip = g_xi    + off;
        const float* zp  = g_zsilu + off;
#pragma unroll 4
        for (int i = 0; i < SUB; i++) {
            float dt = dtp[(size_t)i*CDIM];
            float xi = xip[(size_t)i*CDIM];
            float zv = zp [(size_t)i*CDIM];
            int l = ls + i;
            float e0 = exp2f(dt * a0L);
            float e1 = exp2f(dt * a1L);
            float dbx = dt * xi;
            h0 = fmaf(e0, h0, dbx * bc_s[l*4+0]);
            h1 = fmaf(e1, h1, dbx * bc_s[l*4+1]);
            float y = fmaf(h0, bc_s[l*4+2], fmaf(h1, bc_s[l*4+3], Dp * xi));
            y *= zv;
            __nv_bfloat16 yh = __float2bfloat16(y);
            __nv_bfloat16 yl = __float2bfloat16(y - __bfloat162float(yh));
            uint32_t so = l * TPITCH_B + d * 2;
            *reinterpret_cast<__nv_bfloat16*>(smraw + SM_BH + so) = yh;
            *reinterpret_cast<__nv_bfloat16*>(smraw + SM_BL + so) = yl;
        }
    }
    __syncthreads();

    float acc[4][4][4];
    mma_tile(acc, sb, SM_AH, SM_AL, SM_BH, SM_BL, lane, wm, wn);
    __syncthreads();

    // stage D[o][l] pitch 129 at 0, LN over o, coalesced write
    float* tile = reinterpret_cast<float*>(smraw);
    float* mu_s = tile + 128*129;
    float* rs_s = mu_s + 128;
#pragma unroll
    for (int mf = 0; mf < 4; mf++)
#pragma unroll
        for (int nf = 0; nf < 4; nf++) {
            int row = wm*64 + mf*16 + (lane >> 2);
            int col = wn*32 + nf*8 + (lane & 3) * 2;
            tile[ row      * 129 + col    ] = acc[mf][nf][0];
            tile[ row      * 129 + col + 1] = acc[mf][nf][1];
            tile[(row + 8) * 129 + col    ] = acc[mf][nf][2];
            tile[(row + 8) * 129 + col + 1] = acc[mf][nf][3];
        }
    __syncthreads();

    if (tid < 128) {
        float s = 0.f, q = 0.f;
#pragma unroll 8
        for (int o = 0; o < 128; o++) {
            float v = tile[o*129 + tid];
            s += v;
            q = fmaf(v, v, q);
        }
        float mu = s * (1.0f/128.0f);
        float var = q * (1.0f/128.0f) - mu*mu;
        mu_s[tid] = mu;
        rs_s[tid] = rsqrtf(var + 1e-5f);
    }
    __syncthreads();

    for (int p = tid; p < 128*32; p += 256) {
        int o  = p >> 5;
        int l4 = (p & 31) * 4;
        float g  = gamma[o];
        float bt = beta[o];
        float4 v;
        v.x = fmaf((tile[o*129 + l4+0] - mu_s[l4+0]) * rs_s[l4+0], g, bt);
        v.y = fmaf((tile[o*129 + l4+1] - mu_s[l4+1]) * rs_s[l4+1], g, bt);
        v.z = fmaf((tile[o*129 + l4+2] - mu_s[l4+2]) * rs_s[l4+2], g, bt);
        v.w = fmaf((tile[o*129 + l4+3] - mu_s[l4+3]) * rs_s[l4+3], g, bt);
        *reinterpret_cast<float4*>(&out[((size_t)(b*OUTC + o))*LSEQ + l0 + l4]) = v;
    }
}

// ---------------------------------------------------------------------------
extern "C" void kernel_launch(void* const* d_in, const int* in_sizes, int n_in,
                              void* d_out, int out_size) {
    const float* x          = (const float*)d_in[0];
    const float* in_proj_w  = (const float*)d_in[1];
    const float* conv_w     = (const float*)d_in[2];
    const float* conv_b     = (const float*)d_in[3];
    const float* x_proj_w   = (const float*)d_in[4];
    const float* dt_proj_w  = (const float*)d_in[5];
    const float* dt_proj_b  = (const float*)d_in[6];
    const float* A_log      = (const float*)d_in[7];
    const float* D_param    = (const float*)d_in[8];
    const float* out_proj_w = (const float*)d_in[9];
    const float* ln_gamma   = (const float*)d_in[10];
    const float* ln_beta    = (const float*)d_in[11];
    float* out = (float*)d_out;

    cudaFuncSetAttribute(k_mega1, cudaFuncAttributeMaxDynamicSharedMemorySize, (int)K1_SMEM);
    cudaFuncSetAttribute(k_mega2, cudaFuncAttributeMaxDynamicSharedMemorySize, (int)K3_SMEM);

    k_mega1  <<<dim3(NTILE, B_), 256, K1_SMEM>>>(x, in_proj_w, conv_w, conv_b,
                                                 x_proj_w, dt_proj_w, dt_proj_b, A_log);
    k_combine<<<16, 256>>>();
    k_mega2  <<<dim3(NTILE, B_), 256, K3_SMEM>>>(out_proj_w, ln_gamma, ln_beta,
                                                 A_log, D_param, out);
}

// round 13
// speedup vs baseline: 1.3331x; 1.3331x over previous
#include <cuda_runtime.h>
#include <cuda_bf16.h>
#include <cstdint>
#include <math.h>

#define B_    16
#define CDIM  128
#define LSEQ  9216
#define DSTATE 2
#define DTRANK 8
#define OUTC  128
#define NPROJ 12
#define CHUNK 96
#define NCHUNK 96
#define LOG2E 1.4426950408889634f

// ---------------- device scratch ----------------
__device__ float g_xraw [(size_t)B_*LSEQ*CDIM];
__device__ float g_zsilu[(size_t)B_*LSEQ*CDIM];
__device__ float g_xi   [(size_t)B_*LSEQ*CDIM];
__device__ float g_dt   [(size_t)B_*LSEQ*CDIM];
__device__ float g_y    [(size_t)B_*LSEQ*CDIM];
__device__ float g_bc   [(size_t)B_*LSEQ*4];
__device__ float g_aggA [(size_t)B_*NCHUNK*CDIM*DSTATE];
__device__ float g_aggH [(size_t)B_*NCHUNK*CDIM*DSTATE];
__device__ float g_hinit[(size_t)B_*NCHUNK*CDIM*DSTATE];
// pre-packed A fragments: [mat(3)][mtile(8)][ks(8)][lane(32)] uint4
__device__ uint4 g_waH[3*8*8*32];
__device__ uint4 g_waL[3*8*8*32];

__device__ __forceinline__ float silu_f(float v) {
    return __fdividef(v, 1.0f + __expf(-v));
}
__device__ __forceinline__ uint32_t smem_u32(const void* p) {
    uint32_t a;
    asm("{ .reg .u64 t; cvta.to.shared.u64 t, %1; cvt.u32.u64 %0, t; }" : "=r"(a) : "l"(p));
    return a;
}

#define LDMX4(r0,r1,r2,r3,addr) \
    asm volatile("ldmatrix.sync.aligned.m8n8.x4.shared.b16 {%0,%1,%2,%3}, [%4];" \
        : "=r"(r0),"=r"(r1),"=r"(r2),"=r"(r3) : "r"(addr))
#define MMA_BF16(D, A, B) \
    asm volatile("mma.sync.aligned.m16n8k16.row.col.f32.bf16.bf16.f32 " \
        "{%0,%1,%2,%3}, {%4,%5,%6,%7}, {%8,%9}, {%0,%1,%2,%3};" \
        : "+f"((D)[0]), "+f"((D)[1]), "+f"((D)[2]), "+f"((D)[3]) \
        : "r"((A)[0]), "r"((A)[1]), "r"((A)[2]), "r"((A)[3]), "r"((B)[0]), "r"((B)[1]))

__device__ __forceinline__ void split_pack(float4 v, uint2& hi, uint2& lo) {
    __nv_bfloat162 h0 = __floats2bfloat162_rn(v.x, v.y);
    __nv_bfloat162 h1 = __floats2bfloat162_rn(v.z, v.w);
    float r0 = v.x - __bfloat162float(h0.x);
    float r1 = v.y - __bfloat162float(h0.y);
    float r2 = v.z - __bfloat162float(h1.x);
    float r3 = v.w - __bfloat162float(h1.y);
    __nv_bfloat162 l0 = __floats2bfloat162_rn(r0, r1);
    __nv_bfloat162 l1 = __floats2bfloat162_rn(r2, r3);
    hi = make_uint2(*reinterpret_cast<uint32_t*>(&h0), *reinterpret_cast<uint32_t*>(&h1));
    lo = make_uint2(*reinterpret_cast<uint32_t*>(&l0), *reinterpret_cast<uint32_t*>(&l1));
}

// bf16 tile: [128 rows][128 k], pitch 272 B
#define TPITCH_B 272u
#define TILE_B   (128u*TPITCH_B)      // 34816
#define SM_BH    0u
#define SM_BL    34816u
#define GEMM_SMEM 69632u              // BH + BL; epilogue f32 tile reuses it

// ---------------------------------------------------------------------------
// K0 prep: convert Wi (2 halves) + Wout to bf16 hi/lo fragments in global.
// Grid 3 blocks x 256. Uses the SAME smem layout + ldmatrix addressing as the
// verified GEMM path, so fragments are bit-identical.
// ---------------------------------------------------------------------------
__global__ __launch_bounds__(256)
void k_prep(const float* __restrict__ Wi, const float* __restrict__ Wout) {
    extern __shared__ __align__(16) char smraw[];
    const uint32_t sb = smem_u32(smraw);
    const int mat = blockIdx.x;           // 0: Wi rows 0-127, 1: Wi rows 128-255, 2: Wout
    const float* src = (mat == 2) ? Wout : (Wi + (size_t)mat * 128 * CDIM);
    const int tid = threadIdx.x, lane = tid & 31, wid = tid >> 5;

    for (int idx = tid; idx < 128 * 32; idx += 256) {
        int r = idx >> 5, k4 = (idx & 31) * 4;
        float4 w = *reinterpret_cast<const float4*>(&src[(size_t)r * CDIM + k4]);
        uint2 hi, lo; split_pack(w, hi, lo);
        uint32_t off = r * TPITCH_B + k4 * 2;
        *reinterpret_cast<uint2*>(smraw + SM_BH + off) = hi;
        *reinterpret_cast<uint2*>(smraw + SM_BL + off) = lo;
    }
    __syncthreads();

    const uint32_t a_off = (uint32_t)((lane & 15) * TPITCH_B + ((lane >> 4) * 8) * 2);
    // warp wid handles mtile wid (rows wid*16..wid*16+15)
#pragma unroll
    for (int ks = 0; ks < 8; ks++) {
        uint32_t off = (wid * 16) * TPITCH_B + ks * 32 + a_off;
        uint4 vh, vl;
        LDMX4(vh.x, vh.y, vh.z, vh.w, sb + SM_BH + off);
        LDMX4(vl.x, vl.y, vl.z, vl.w, sb + SM_BL + off);
        int gi = ((mat * 8 + wid) * 8 + ks) * 32 + lane;
        g_waH[gi] = vh;
        g_waL[gi] = vl;
    }
}

// ---------------------------------------------------------------------------
// 128x128x128 3-term hi/lo MMA tile, A fragments from global, B from smem.
// ---------------------------------------------------------------------------
__device__ __forceinline__ void mma_tile_ga(float (*d)[4][4], uint32_t sb,
        const uint4* __restrict__ gaH, const uint4* __restrict__ gaL,
        int lane, int wm, int wn) {
    const uint32_t b_off = (uint32_t)((((lane >> 4) & 1) * 8 + (lane & 7)) * TPITCH_B
                                      + (((lane >> 3) & 1) * 8) * 2);
#pragma unroll
    for (int i = 0; i < 4; i++)
#pragma unroll
        for (int j = 0; j < 4; j++)
#pragma unroll
            for (int q = 0; q < 4; q++) d[i][j][q] = 0.f;

#pragma unroll 1
    for (int ks = 0; ks < 8; ks++) {
        uint4 ah4[4], al4[4];
#pragma unroll
        for (int mf = 0; mf < 4; mf++) {
            int gi = ((wm * 4 + mf) * 8 + ks) * 32 + lane;
            ah4[mf] = gaH[gi];
            al4[mf] = gaL[gi];
        }
        const uint32_t kb = ks * 32;
        uint32_t bh[4][2], bl[4][2];
#pragma unroll
        for (int p = 0; p < 2; p++) {
            uint32_t off = (wn*32 + p*16) * TPITCH_B + kb + b_off;
            LDMX4(bh[2*p][0], bh[2*p][1], bh[2*p+1][0], bh[2*p+1][1], sb + SM_BH + off);
            LDMX4(bl[2*p][0], bl[2*p][1], bl[2*p+1][0], bl[2*p+1][1], sb + SM_BL + off);
        }
#pragma unroll
        for (int mf = 0; mf < 4; mf++) {
            const uint32_t* ah = reinterpret_cast<const uint32_t*>(&ah4[mf]);
            const uint32_t* al = reinterpret_cast<const uint32_t*>(&al4[mf]);
#pragma unroll
            for (int nf = 0; nf < 4; nf++) {
                MMA_BF16(d[mf][nf], ah, bh[nf]);
                MMA_BF16(d[mf][nf], ah, bl[nf]);
                MMA_BF16(d[mf][nf], al, bh[nf]);
            }
        }
    }
}

// ---------------------------------------------------------------------------
// K1: in_proj. Grid (72, 2, 16): M = 128 e (half), N = 128 tokens, K = 128.
// ---------------------------------------------------------------------------
__global__ __launch_bounds__(256)
void k_inproj_mma(const float* __restrict__ x) {
    extern __shared__ __align__(16) char smraw[];
    const uint32_t sb = smem_u32(smraw);
    const int tid  = threadIdx.x;
    const int lane = tid & 31;
    const int wid  = tid >> 5;
    const int wm   = wid >> 2;
    const int wn   = wid & 3;
    const int b    = blockIdx.z;
    const int half = blockIdx.y;
    const int l0   = blockIdx.x * 128;

    // B: x tile [k][l] -> [l][k] bf16 hi/lo
    {
        const float* xb = x + (size_t)b * CDIM * LSEQ;
        for (int idx = tid; idx < 128 * 32; idx += 256) {
            int k = idx >> 5, l4 = (idx & 31) * 4;
            float4 v = *reinterpret_cast<const float4*>(&xb[(size_t)k * LSEQ + l0 + l4]);
            float vv[4] = {v.x, v.y, v.z, v.w};
#pragma unroll
            for (int i = 0; i < 4; i++) {
                __nv_bfloat16 h = __float2bfloat16(vv[i]);
                __nv_bfloat16 l = __float2bfloat16(vv[i] - __bfloat162float(h));
                uint32_t off = (l4 + i) * TPITCH_B + k * 2;
                *reinterpret_cast<__nv_bfloat16*>(smraw + SM_BH + off) = h;
                *reinterpret_cast<__nv_bfloat16*>(smraw + SM_BL + off) = l;
            }
        }
    }
    __syncthreads();

    float acc[4][4][4];
    mma_tile_ga(acc, sb, g_waH + half * 2048, g_waL + half * 2048, lane, wm, wn);
    __syncthreads();

    // stage D[e][l] into f32 tile (pitch 129), then coalesced write
    float* tile = reinterpret_cast<float*>(smraw);   // [128][129]
#pragma unroll
    for (int mf = 0; mf < 4; mf++)
#pragma unroll
        for (int nf = 0; nf < 4; nf++) {
            int row = wm*64 + mf*16 + (lane >> 2);
            int col = wn*32 + nf*8 + (lane & 3) * 2;
            tile[ row      * 129 + col    ] = acc[mf][nf][0];
            tile[ row      * 129 + col + 1] = acc[mf][nf][1];
            tile[(row + 8) * 129 + col    ] = acc[mf][nf][2];
            tile[(row + 8) * 129 + col + 1] = acc[mf][nf][3];
        }
    __syncthreads();

    float* dst = (half == 0 ? g_xraw : g_zsilu);
    for (int idx = tid; idx < 128 * 32; idx += 256) {
        int l = idx >> 5, e4 = (idx & 31) * 4;
        float4 v;
        v.x = tile[(e4+0)*129 + l];
        v.y = tile[(e4+1)*129 + l];
        v.z = tile[(e4+2)*129 + l];
        v.w = tile[(e4+3)*129 + l];
        if (half == 1) { v.x = silu_f(v.x); v.y = silu_f(v.y); v.z = silu_f(v.z); v.w = silu_f(v.w); }
        *reinterpret_cast<float4*>(&dst[((size_t)b * LSEQ + l0 + l) * CDIM + e4]) = v;
    }
}

// ---------------------------------------------------------------------------
// K2: phaseA — 256 threads. conv+silu -> xi, x_dbl -> bc, dt, chunk aggregates.
// ---------------------------------------------------------------------------
#define SM2_FLOATS (96*132 + 12*132 + 96*16)

__global__ __launch_bounds__(256)
void k_phaseA(const float* __restrict__ conv_w, const float* __restrict__ conv_b,
              const float* __restrict__ x_proj_w, const float* __restrict__ dt_proj_w,
              const float* __restrict__ dt_proj_b, const float* __restrict__ A_log) {
    extern __shared__ float sm[];
    float* xi_s = sm;
    float* xw_s = sm + 96*132;
    float* xd_s = xw_s + 12*132;

    const int ch = blockIdx.x;
    const int b  = blockIdx.y;
    const int l0 = ch * CHUNK;
    const int tid = threadIdx.x;
    const int d    = tid & 127;
    const int half = tid >> 7;

    for (int i = tid; i < NPROJ*CDIM; i += 256)
        xw_s[(i >> 7)*132 + (i & 127)] = x_proj_w[i];

    {
        const float cw0 = conv_w[d*4+0], cw1 = conv_w[d*4+1];
        const float cw2 = conv_w[d*4+2], cw3 = conv_w[d*4+3];
        const float cb  = conv_b[d];
        const float* xr = g_xraw + (size_t)b * LSEQ * CDIM;
        float* xo = g_xi + ((size_t)b * LSEQ + l0) * CDIM + d;
        const int ls = half * 48;
        const int la0 = l0 + ls;
        float p0 = (la0 >= 3) ? xr[(size_t)(la0-3)*CDIM + d] : 0.f;
        float p1 = (la0 >= 2) ? xr[(size_t)(la0-2)*CDIM + d] : 0.f;
        float p2 = (la0 >= 1) ? xr[(size_t)(la0-1)*CDIM + d] : 0.f;
#pragma unroll 4
        for (int l = ls; l < ls + 48; l++) {
            float c = xr[(size_t)(l0+l)*CDIM + d];
            float a = fmaf(cw0,p0, fmaf(cw1,p1, fmaf(cw2,p2, fmaf(cw3,c, cb))));
            float v = silu_f(a);
            xi_s[l*132 + d] = v;
            xo[(size_t)l*CDIM] = v;
            p0 = p1; p1 = p2; p2 = c;
        }
    }
    __syncthreads();

    {
        float* bco = g_bc + ((size_t)b * LSEQ + l0) * 4;
        for (int p = tid; p < CHUNK*NPROJ; p += 256) {
            int l = p / 12, j = p - l*12;
            const float4* xr4 = reinterpret_cast<const float4*>(&xi_s[l*132]);
            const float4* wr4 = reinterpret_cast<const float4*>(&xw_s[j*132]);
            float s = 0.f;
#pragma unroll
            for (int k = 0; k < 32; k++) {
                float4 xa = xr4[k], wa = wr4[k];
                s = fmaf(xa.x, wa.x, s); s = fmaf(xa.y, wa.y, s);
                s = fmaf(xa.z, wa.z, s); s = fmaf(xa.w, wa.w, s);
            }
            xd_s[l*16 + j] = s;
            if (j >= 8) bco[l*4 + (j-8)] = s;
        }
    }
    __syncthreads();

    if (tid < 128) {
        float wdt[DTRANK];
#pragma unroll
        for (int r = 0; r < DTRANK; r++) wdt[r] = dt_proj_w[d*DTRANK + r];
        const float bdt = dt_proj_b[d];
        const float a0L = -__expf(A_log[2*d+0]) * LOG2E;
        const float a1L = -__expf(A_log[2*d+1]) * LOG2E;
        float* dto = g_dt + ((size_t)b * LSEQ + l0) * CDIM + d;

        float h0 = 0.f, h1 = 0.f, sdt = 0.f;
#pragma unroll 2
        for (int l = 0; l < CHUNK; l++) {
            const float* xd = &xd_s[l*16];
            float t = bdt;
#pragma unroll
            for (int r = 0; r < DTRANK; r++) t = fmaf(xd[r], wdt[r], t);
            float ex = __expf(t);
            float dt = (t > 20.f) ? t : __logf(1.f + ex);
            dto[(size_t)l*CDIM] = dt;
            sdt += dt;
            float e0 = exp2f(dt * a0L);
            float e1 = exp2f(dt * a1L);
            float dbx = dt * xi_s[l*132 + d];
            h0 = fmaf(e0, h0, dbx * xd[8]);
            h1 = fmaf(e1, h1, dbx * xd[9]);
        }
        const size_t base = (((size_t)b*NCHUNK + ch)*CDIM + d)*DSTATE;
        g_aggA[base+0] = exp2f(a0L * sdt);
        g_aggA[base+1] = exp2f(a1L * sdt);
        g_aggH[base+0] = h0;
        g_aggH[base+1] = h1;
    }
}

// ---------------------------------------------------------------------------
// K3: chain chunk aggregates
// ---------------------------------------------------------------------------
__global__ __launch_bounds__(256)
void k_combine() {
    const int g = blockIdx.x * blockDim.x + threadIdx.x;
    const int b = g >> 8;
    const int rem = g & 255;
    float h = 0.f;
    for (int ch = 0; ch < NCHUNK; ch++) {
        const size_t idx = (((size_t)b*NCHUNK + ch) * CDIM * DSTATE) + rem;
        g_hinit[idx] = h;
        h = fmaf(g_aggA[idx], h, g_aggH[idx]);
    }
}

// ---------------------------------------------------------------------------
// K4: scan
// ---------------------------------------------------------------------------
__global__ __launch_bounds__(128)
void k_scan(const float* __restrict__ A_log, const float* __restrict__ D_param) {
    __shared__ float bc_s[CHUNK*4];
    const int ch = blockIdx.x;
    const int b  = blockIdx.y;
    const int l0 = ch * CHUNK;
    const int d  = threadIdx.x;

    {
        const float* bcg = g_bc + ((size_t)b * LSEQ + l0) * 4;
        for (int i = d; i < CHUNK*4; i += 128) bc_s[i] = bcg[i];
    }
    const float a0L = -__expf(A_log[2*d+0]) * LOG2E;
    const float a1L = -__expf(A_log[2*d+1]) * LOG2E;
    const float Dp  = D_param[d];
    const size_t base = (((size_t)b*NCHUNK + ch)*CDIM + d)*DSTATE;
    float h0 = g_hinit[base+0];
    float h1 = g_hinit[base+1];

    const size_t off = ((size_t)b * LSEQ + l0) * CDIM + d;
    const float* dtp = g_dt    + off;
    const float* xip = g_xi    + off;
    const float* zp  = g_zsilu + off;
    float*       yp  = g_y     + off;
    __syncthreads();

#pragma unroll 4
    for (int l = 0; l < CHUNK; l++) {
        float dt = dtp[(size_t)l*CDIM];
        float xi = xip[(size_t)l*CDIM];
        float zv = zp [(size_t)l*CDIM];
        float e0 = exp2f(dt * a0L);
        float e1 = exp2f(dt * a1L);
        float dbx = dt * xi;
        h0 = fmaf(e0, h0, dbx * bc_s[l*4+0]);
        h1 = fmaf(e1, h1, dbx * bc_s[l*4+1]);
        float y = fmaf(h0, bc_s[l*4+2], fmaf(h1, bc_s[l*4+3], Dp * xi));
        yp[(size_t)l*CDIM] = y * zv;
    }
}

// ---------------------------------------------------------------------------
// K5: out_proj + fused LayerNorm. Grid (72, 16): M = 128 o, N = 128 tokens.
// ---------------------------------------------------------------------------
__global__ __launch_bounds__(256)
void k_outproj_mma(const float* __restrict__ gamma, const float* __restrict__ beta,
                   float* __restrict__ out) {
    extern __shared__ __align__(16) char smraw[];
    const uint32_t sb = smem_u32(smraw);
    const int tid  = threadIdx.x;
    const int lane = tid & 31;
    const int wid  = tid >> 5;
    const int wm   = wid >> 2;
    const int wn   = wid & 3;
    const int b    = blockIdx.y;
    const int l0   = blockIdx.x * 128;

    // B: y tile [l][k] bf16 hi/lo
    {
        const float* yb = g_y + ((size_t)b * LSEQ + l0) * CDIM;
        for (int idx = tid; idx < 128 * 32; idx += 256) {
            int l = idx >> 5, k4 = (idx & 31) * 4;
            float4 v = *reinterpret_cast<const float4*>(&yb[(size_t)l * CDIM + k4]);
            uint2 hi, lo; split_pack(v, hi, lo);
            uint32_t off = l * TPITCH_B + k4 * 2;
            *reinterpret_cast<uint2*>(smraw + SM_BH + off) = hi;
            *reinterpret_cast<uint2*>(smraw + SM_BL + off) = lo;
        }
    }
    __syncthreads();

    float acc[4][4][4];
    mma_tile_ga(acc, sb, g_waH + 2 * 2048, g_waL + 2 * 2048, lane, wm, wn);
    __syncthreads();

    // stage D[o][l] (pitch 129), LN over o, coalesced write
    float* tile = reinterpret_cast<float*>(smraw);   // [128][129]
    float* mu_s = tile + 128*129;
    float* rs_s = mu_s + 128;
#pragma unroll
    for (int mf = 0; mf < 4; mf++)
#pragma unroll
        for (int nf = 0; nf < 4; nf++) {
            int row = wm*64 + mf*16 + (lane >> 2);
            int col = wn*32 + nf*8 + (lane & 3) * 2;
            tile[ row      * 129 + col    ] = acc[mf][nf][0];
            tile[ row      * 129 + col + 1] = acc[mf][nf][1];
            tile[(row + 8) * 129 + col    ] = acc[mf][nf][2];
            tile[(row + 8) * 129 + col + 1] = acc[mf][nf][3];
        }
    __syncthreads();

    if (tid < 128) {
        float s = 0.f, q = 0.f;
#pragma unroll 8
        for (int o = 0; o < 128; o++) {
            float v = tile[o*129 + tid];
            s += v;
            q = fmaf(v, v, q);
        }
        float mu = s * (1.0f/128.0f);
        float var = q * (1.0f/128.0f) - mu*mu;
        mu_s[tid] = mu;
        rs_s[tid] = rsqrtf(var + 1e-5f);
    }
    __syncthreads();

    for (int p = tid; p < 128*32; p += 256) {
        int o  = p >> 5;
        int l4 = (p & 31) * 4;
        float g  = gamma[o];
        float bt = beta[o];
        float4 v;
        v.x = fmaf((tile[o*129 + l4+0] - mu_s[l4+0]) * rs_s[l4+0], g, bt);
        v.y = fmaf((tile[o*129 + l4+1] - mu_s[l4+1]) * rs_s[l4+1], g, bt);
        v.z = fmaf((tile[o*129 + l4+2] - mu_s[l4+2]) * rs_s[l4+2], g, bt);
        v.w = fmaf((tile[o*129 + l4+3] - mu_s[l4+3]) * rs_s[l4+3], g, bt);
        *reinterpret_cast<float4*>(&out[((size_t)(b*OUTC + o))*LSEQ + l0 + l4]) = v;
    }
}

// ---------------------------------------------------------------------------
extern "C" void kernel_launch(void* const* d_in, const int* in_sizes, int n_in,
                              void* d_out, int out_size) {
    const float* x          = (const float*)d_in[0];
    const float* in_proj_w  = (const float*)d_in[1];
    const float* conv_w     = (const float*)d_in[2];
    const float* conv_b     = (const float*)d_in[3];
    const float* x_proj_w   = (const float*)d_in[4];
    const float* dt_proj_w  = (const float*)d_in[5];
    const float* dt_proj_b  = (const float*)d_in[6];
    const float* A_log      = (const float*)d_in[7];
    const float* D_param    = (const float*)d_in[8];
    const float* out_proj_w = (const float*)d_in[9];
    const float* ln_gamma   = (const float*)d_in[10];
    const float* ln_beta    = (const float*)d_in[11];
    float* out = (float*)d_out;

    const int sm2 = SM2_FLOATS * sizeof(float);
    cudaFuncSetAttribute(k_prep,        cudaFuncAttributeMaxDynamicSharedMemorySize, (int)GEMM_SMEM);
    cudaFuncSetAttribute(k_inproj_mma,  cudaFuncAttributeMaxDynamicSharedMemorySize, (int)GEMM_SMEM);
    cudaFuncSetAttribute(k_phaseA,      cudaFuncAttributeMaxDynamicSharedMemorySize, sm2);
    cudaFuncSetAttribute(k_outproj_mma, cudaFuncAttributeMaxDynamicSharedMemorySize, (int)GEMM_SMEM);

    k_prep       <<<3, 256, GEMM_SMEM>>>(in_proj_w, out_proj_w);
    k_inproj_mma <<<dim3(LSEQ/128, 2, B_), 256, GEMM_SMEM>>>(x);
    k_phaseA     <<<dim3(NCHUNK, B_), 256, sm2>>>(conv_w, conv_b, x_proj_w,
                                                  dt_proj_w, dt_proj_b, A_log);
    k_combine    <<<16, 256>>>();
    k_scan       <<<dim3(NCHUNK, B_), 128>>>(A_log, D_param);
    k_outproj_mma<<<dim3(LSEQ/128, B_), 256, GEMM_SMEM>>>(ln_gamma, ln_beta, out);
}

// round 15
// speedup vs baseline: 1.4635x; 1.0978x over previous
#include <cuda_runtime.h>
#include <cuda_bf16.h>
#include <cstdint>
#include <math.h>

#define B_    16
#define CDIM  128
#define LSEQ  9216
#define DSTATE 2
#define DTRANK 8
#define OUTC  128
#define NPROJ 12
#define CHUNK 96
#define NCHUNK 96
#define NSUBB 192          // 48-token subchunks per batch
#define NGRP  16           // groups of 12 subchunks
#define GSZ   12
#define LOG2E 1.4426950408889634f

// ---------------- device scratch ----------------
__device__ float g_xraw [(size_t)B_*LSEQ*CDIM];
__device__ float g_zsilu[(size_t)B_*LSEQ*CDIM];
__device__ float g_xi   [(size_t)B_*LSEQ*CDIM];
__device__ float g_dt   [(size_t)B_*LSEQ*CDIM];
__device__ float g_y    [(size_t)B_*LSEQ*CDIM];
__device__ float g_bc   [(size_t)B_*LSEQ*4];
__device__ float g_aggA [(size_t)B_*NSUBB*CDIM*DSTATE];
__device__ float g_aggH [(size_t)B_*NSUBB*CDIM*DSTATE];
__device__ float g_hinit[(size_t)B_*NSUBB*CDIM*DSTATE];
__device__ float g_grpA [(size_t)B_*NGRP*CDIM*DSTATE];
__device__ float g_grpH [(size_t)B_*NGRP*CDIM*DSTATE];
__device__ float g_ghin [(size_t)B_*NGRP*CDIM*DSTATE];
// pre-packed A fragments: [mat(3)][mtile(8)][ks(8)][lane(32)] uint4
__device__ uint4 g_waH[3*8*8*32];
__device__ uint4 g_waL[3*8*8*32];

__device__ __forceinline__ float silu_f(float v) {
    return __fdividef(v, 1.0f + __expf(-v));
}
__device__ __forceinline__ uint32_t smem_u32(const void* p) {
    uint32_t a;
    asm("{ .reg .u64 t; cvta.to.shared.u64 t, %1; cvt.u32.u64 %0, t; }" : "=r"(a) : "l"(p));
    return a;
}

#define LDMX4(r0,r1,r2,r3,addr) \
    asm volatile("ldmatrix.sync.aligned.m8n8.x4.shared.b16 {%0,%1,%2,%3}, [%4];" \
        : "=r"(r0),"=r"(r1),"=r"(r2),"=r"(r3) : "r"(addr))
#define MMA_BF16(D, A, B) \
    asm volatile("mma.sync.aligned.m16n8k16.row.col.f32.bf16.bf16.f32 " \
        "{%0,%1,%2,%3}, {%4,%5,%6,%7}, {%8,%9}, {%0,%1,%2,%3};" \
        : "+f"((D)[0]), "+f"((D)[1]), "+f"((D)[2]), "+f"((D)[3]) \
        : "r"((A)[0]), "r"((A)[1]), "r"((A)[2]), "r"((A)[3]), "r"((B)[0]), "r"((B)[1]))

__device__ __forceinline__ void split_pack(float4 v, uint2& hi, uint2& lo) {
    __nv_bfloat162 h0 = __floats2bfloat162_rn(v.x, v.y);
    __nv_bfloat162 h1 = __floats2bfloat162_rn(v.z, v.w);
    float r0 = v.x - __bfloat162float(h0.x);
    float r1 = v.y - __bfloat162float(h0.y);
    float r2 = v.z - __bfloat162float(h1.x);
    float r3 = v.w - __bfloat162float(h1.y);
    __nv_bfloat162 l0 = __floats2bfloat162_rn(r0, r1);
    __nv_bfloat162 l1 = __floats2bfloat162_rn(r2, r3);
    hi = make_uint2(*reinterpret_cast<uint32_t*>(&h0), *reinterpret_cast<uint32_t*>(&h1));
    lo = make_uint2(*reinterpret_cast<uint32_t*>(&l0), *reinterpret_cast<uint32_t*>(&l1));
}

// bf16 tile: [128 rows][128 k], pitch 272 B
#define TPITCH_B 272u
#define TILE_B   (128u*TPITCH_B)      // 34816
#define SM_BH    0u
#define SM_BL    34816u
#define GEMM_SMEM 69632u

// ---------------------------------------------------------------------------
// K0 prep: Wi (2 halves) + Wout -> bf16 hi/lo fragments in global.
// ---------------------------------------------------------------------------
__global__ __launch_bounds__(256)
void k_prep(const float* __restrict__ Wi, const float* __restrict__ Wout) {
    extern __shared__ __align__(16) char smraw[];
    const uint32_t sb = smem_u32(smraw);
    const int mat = blockIdx.x;
    const float* src = (mat == 2) ? Wout : (Wi + (size_t)mat * 128 * CDIM);
    const int tid = threadIdx.x, lane = tid & 31, wid = tid >> 5;

    for (int idx = tid; idx < 128 * 32; idx += 256) {
        int r = idx >> 5, k4 = (idx & 31) * 4;
        float4 w = *reinterpret_cast<const float4*>(&src[(size_t)r * CDIM + k4]);
        uint2 hi, lo; split_pack(w, hi, lo);
        uint32_t off = r * TPITCH_B + k4 * 2;
        *reinterpret_cast<uint2*>(smraw + SM_BH + off) = hi;
        *reinterpret_cast<uint2*>(smraw + SM_BL + off) = lo;
    }
    __syncthreads();

    const uint32_t a_off = (uint32_t)((lane & 15) * TPITCH_B + ((lane >> 4) * 8) * 2);
#pragma unroll
    for (int ks = 0; ks < 8; ks++) {
        uint32_t off = (wid * 16) * TPITCH_B + ks * 32 + a_off;
        uint4 vh, vl;
        LDMX4(vh.x, vh.y, vh.z, vh.w, sb + SM_BH + off);
        LDMX4(vl.x, vl.y, vl.z, vl.w, sb + SM_BL + off);
        int gi = ((mat * 8 + wid) * 8 + ks) * 32 + lane;
        g_waH[gi] = vh;
        g_waL[gi] = vl;
    }
}

// ---------------------------------------------------------------------------
// 128x128x128 3-term hi/lo MMA tile, A fragments from global, B from smem.
// ---------------------------------------------------------------------------
__device__ __forceinline__ void mma_tile_ga(float (*d)[4][4], uint32_t sb,
        const uint4* __restrict__ gaH, const uint4* __restrict__ gaL,
        int lane, int wm, int wn) {
    const uint32_t b_off = (uint32_t)((((lane >> 4) & 1) * 8 + (lane & 7)) * TPITCH_B
                                      + (((lane >> 3) & 1) * 8) * 2);
#pragma unroll
    for (int i = 0; i < 4; i++)
#pragma unroll
        for (int j = 0; j < 4; j++)
#pragma unroll
            for (int q = 0; q < 4; q++) d[i][j][q] = 0.f;

#pragma unroll 1
    for (int ks = 0; ks < 8; ks++) {
        uint4 ah4[4], al4[4];
#pragma unroll
        for (int mf = 0; mf < 4; mf++) {
            int gi = ((wm * 4 + mf) * 8 + ks) * 32 + lane;
            ah4[mf] = gaH[gi];
            al4[mf] = gaL[gi];
        }
        const uint32_t kb = ks * 32;
        uint32_t bh[4][2], bl[4][2];
#pragma unroll
        for (int p = 0; p < 2; p++) {
            uint32_t off = (wn*32 + p*16) * TPITCH_B + kb + b_off;
            LDMX4(bh[2*p][0], bh[2*p][1], bh[2*p+1][0], bh[2*p+1][1], sb + SM_BH + off);
            LDMX4(bl[2*p][0], bl[2*p][1], bl[2*p+1][0], bl[2*p+1][1], sb + SM_BL + off);
        }
#pragma unroll
        for (int mf = 0; mf < 4; mf++) {
            const uint32_t* ah = reinterpret_cast<const uint32_t*>(&ah4[mf]);
            const uint32_t* al = reinterpret_cast<const uint32_t*>(&al4[mf]);
#pragma unroll
            for (int nf = 0; nf < 4; nf++) {
                MMA_BF16(d[mf][nf], ah, bh[nf]);
                MMA_BF16(d[mf][nf], ah, bl[nf]);
                MMA_BF16(d[mf][nf], al, bh[nf]);
            }
        }
    }
}

// ---------------------------------------------------------------------------
// K1: in_proj. Grid (72, 2, 16).
// ---------------------------------------------------------------------------
__global__ __launch_bounds__(256)
void k_inproj_mma(const float* __restrict__ x) {
    extern __shared__ __align__(16) char smraw[];
    const uint32_t sb = smem_u32(smraw);
    const int tid  = threadIdx.x;
    const int lane = tid & 31;
    const int wid  = tid >> 5;
    const int wm   = wid >> 2;
    const int wn   = wid & 3;
    const int b    = blockIdx.z;
    const int half = blockIdx.y;
    const int l0   = blockIdx.x * 128;

    {
        const float* xb = x + (size_t)b * CDIM * LSEQ;
        for (int idx = tid; idx < 128 * 32; idx += 256) {
            int k = idx >> 5, l4 = (idx & 31) * 4;
            float4 v = *reinterpret_cast<const float4*>(&xb[(size_t)k * LSEQ + l0 + l4]);
            float vv[4] = {v.x, v.y, v.z, v.w};
#pragma unroll
            for (int i = 0; i < 4; i++) {
                __nv_bfloat16 h = __float2bfloat16(vv[i]);
                __nv_bfloat16 l = __float2bfloat16(vv[i] - __bfloat162float(h));
                uint32_t off = (l4 + i) * TPITCH_B + k * 2;
                *reinterpret_cast<__nv_bfloat16*>(smraw + SM_BH + off) = h;
                *reinterpret_cast<__nv_bfloat16*>(smraw + SM_BL + off) = l;
            }
        }
    }
    __syncthreads();

    float acc[4][4][4];
    mma_tile_ga(acc, sb, g_waH + half * 2048, g_waL + half * 2048, lane, wm, wn);
    __syncthreads();

    float* tile = reinterpret_cast<float*>(smraw);   // [128][129]
#pragma unroll
    for (int mf = 0; mf < 4; mf++)
#pragma unroll
        for (int nf = 0; nf < 4; nf++) {
            int row = wm*64 + mf*16 + (lane >> 2);
            int col = wn*32 + nf*8 + (lane & 3) * 2;
            tile[ row      * 129 + col    ] = acc[mf][nf][0];
            tile[ row      * 129 + col + 1] = acc[mf][nf][1];
            tile[(row + 8) * 129 + col    ] = acc[mf][nf][2];
            tile[(row + 8) * 129 + col + 1] = acc[mf][nf][3];
        }
    __syncthreads();

    float* dst = (half == 0 ? g_xraw : g_zsilu);
    for (int idx = tid; idx < 128 * 32; idx += 256) {
        int l = idx >> 5, e4 = (idx & 31) * 4;
        float4 v;
        v.x = tile[(e4+0)*129 + l];
        v.y = tile[(e4+1)*129 + l];
        v.z = tile[(e4+2)*129 + l];
        v.w = tile[(e4+3)*129 + l];
        if (half == 1) { v.x = silu_f(v.x); v.y = silu_f(v.y); v.z = silu_f(v.z); v.w = silu_f(v.w); }
        *reinterpret_cast<float4*>(&dst[((size_t)b * LSEQ + l0 + l) * CDIM + e4]) = v;
    }
}

// ---------------------------------------------------------------------------
// K2: phaseA — conv+silu -> xi, x_dbl -> bc, dt + 48-token subchunk aggregates
// (both halves active). Grid (NCHUNK, B_), 256 threads.
// ---------------------------------------------------------------------------
#define SM2_FLOATS (96*132 + 12*132 + 96*16)

__global__ __launch_bounds__(256)
void k_phaseA(const float* __restrict__ conv_w, const float* __restrict__ conv_b,
              const float* __restrict__ x_proj_w, const float* __restrict__ dt_proj_w,
              const float* __restrict__ dt_proj_b, const float* __restrict__ A_log) {
    extern __shared__ float sm[];
    float* xi_s = sm;
    float* xw_s = sm + 96*132;
    float* xd_s = xw_s + 12*132;

    const int ch = blockIdx.x;
    const int b  = blockIdx.y;
    const int l0 = ch * CHUNK;
    const int tid = threadIdx.x;
    const int d    = tid & 127;
    const int half = tid >> 7;

    for (int i = tid; i < NPROJ*CDIM; i += 256)
        xw_s[(i >> 7)*132 + (i & 127)] = x_proj_w[i];

    {
        const float cw0 = conv_w[d*4+0], cw1 = conv_w[d*4+1];
        const float cw2 = conv_w[d*4+2], cw3 = conv_w[d*4+3];
        const float cb  = conv_b[d];
        const float* xr = g_xraw + (size_t)b * LSEQ * CDIM;
        float* xo = g_xi + ((size_t)b * LSEQ + l0) * CDIM + d;
        const int ls = half * 48;
        const int la0 = l0 + ls;
        float p0 = (la0 >= 3) ? xr[(size_t)(la0-3)*CDIM + d] : 0.f;
        float p1 = (la0 >= 2) ? xr[(size_t)(la0-2)*CDIM + d] : 0.f;
        float p2 = (la0 >= 1) ? xr[(size_t)(la0-1)*CDIM + d] : 0.f;
#pragma unroll 4
        for (int l = ls; l < ls + 48; l++) {
            float c = xr[(size_t)(l0+l)*CDIM + d];
            float a = fmaf(cw0,p0, fmaf(cw1,p1, fmaf(cw2,p2, fmaf(cw3,c, cb))));
            float v = silu_f(a);
            xi_s[l*132 + d] = v;
            xo[(size_t)l*CDIM] = v;
            p0 = p1; p1 = p2; p2 = c;
        }
    }
    __syncthreads();

    {
        float* bco = g_bc + ((size_t)b * LSEQ + l0) * 4;
        for (int p = tid; p < CHUNK*NPROJ; p += 256) {
            int l = p / 12, j = p - l*12;
            const float4* xr4 = reinterpret_cast<const float4*>(&xi_s[l*132]);
            const float4* wr4 = reinterpret_cast<const float4*>(&xw_s[j*132]);
            float s = 0.f;
#pragma unroll
            for (int k = 0; k < 32; k++) {
                float4 xa = xr4[k], wa = wr4[k];
                s = fmaf(xa.x, wa.x, s); s = fmaf(xa.y, wa.y, s);
                s = fmaf(xa.z, wa.z, s); s = fmaf(xa.w, wa.w, s);
            }
            xd_s[l*16 + j] = s;
            if (j >= 8) bco[l*4 + (j-8)] = s;
        }
    }
    __syncthreads();

    // dt + 48-token subchunk aggregates: thread (d, half)
    {
        float wdt[DTRANK];
#pragma unroll
        for (int r = 0; r < DTRANK; r++) wdt[r] = dt_proj_w[d*DTRANK + r];
        const float bdt = dt_proj_b[d];
        const float a0L = -__expf(A_log[2*d+0]) * LOG2E;
        const float a1L = -__expf(A_log[2*d+1]) * LOG2E;
        const int ls = half * 48;
        float* dto = g_dt + ((size_t)b * LSEQ + l0 + ls) * CDIM + d;

        float h0 = 0.f, h1 = 0.f, sdt = 0.f;
#pragma unroll 2
        for (int i = 0; i < 48; i++) {
            const float* xd = &xd_s[(ls + i)*16];
            float t = bdt;
#pragma unroll
            for (int r = 0; r < DTRANK; r++) t = fmaf(xd[r], wdt[r], t);
            float ex = __expf(t);
            float dt = (t > 20.f) ? t : __logf(1.f + ex);
            dto[(size_t)i*CDIM] = dt;
            sdt += dt;
            float e0 = exp2f(dt * a0L);
            float e1 = exp2f(dt * a1L);
            float dbx = dt * xi_s[(ls + i)*132 + d];
            h0 = fmaf(e0, h0, dbx * xd[8]);
            h1 = fmaf(e1, h1, dbx * xd[9]);
        }
        const int sub = ch * 2 + half;
        const size_t base = (((size_t)b*NSUBB + sub)*CDIM + d)*DSTATE;
        g_aggA[base+0] = exp2f(a0L * sdt);
        g_aggA[base+1] = exp2f(a1L * sdt);
        g_aggH[base+0] = h0;
        g_aggH[base+1] = h1;
    }
}

// ---------------------------------------------------------------------------
// K3 a/b/c: two-level combine over 192 subchunks = 16 groups x 12.
// ---------------------------------------------------------------------------
__global__ __launch_bounds__(256)
void k_comb1() {    // per-group aggregate. grid (NGRP, B_)
    const int g = blockIdx.x, b = blockIdx.y, rem = threadIdx.x;
    float A0 = 1.f, h = 0.f;
#pragma unroll
    for (int i = 0; i < GSZ; i++) {
        const size_t idx = (((size_t)b*NSUBB + g*GSZ + i) * CDIM * DSTATE) + rem;
        float a = g_aggA[idx];
        h = fmaf(a, h, g_aggH[idx]);
        A0 *= a;
    }
    const size_t o = (((size_t)b*NGRP + g) * CDIM * DSTATE) + rem;
    g_grpA[o] = A0;
    g_grpH[o] = h;
}

__global__ __launch_bounds__(256)
void k_comb2() {    // chain groups. grid (B_)
    const int b = blockIdx.x, rem = threadIdx.x;
    float h = 0.f;
#pragma unroll
    for (int g = 0; g < NGRP; g++) {
        const size_t o = (((size_t)b*NGRP + g) * CDIM * DSTATE) + rem;
        g_ghin[o] = h;
        h = fmaf(g_grpA[o], h, g_grpH[o]);
    }
}

__global__ __launch_bounds__(256)
void k_comb3() {    // within-group entries. grid (NGRP, B_)
    const int g = blockIdx.x, b = blockIdx.y, rem = threadIdx.x;
    float h = g_ghin[(((size_t)b*NGRP + g) * CDIM * DSTATE) + rem];
#pragma unroll
    for (int i = 0; i < GSZ; i++) {
        const size_t idx = (((size_t)b*NSUBB + g*GSZ + i) * CDIM * DSTATE) + rem;
        g_hinit[idx] = h;
        h = fmaf(g_aggA[idx], h, g_aggH[idx]);
    }
}

// ---------------------------------------------------------------------------
// K4: scan — 256 threads (d, half), each 48 tokens.
// ---------------------------------------------------------------------------
__global__ __launch_bounds__(256)
void k_scan(const float* __restrict__ A_log, const float* __restrict__ D_param) {
    __shared__ float bc_s[CHUNK*4];
    const int ch = blockIdx.x;
    const int b  = blockIdx.y;
    const int l0 = ch * CHUNK;
    const int tid = threadIdx.x;
    const int d    = tid & 127;
    const int half = tid >> 7;

    {
        const float* bcg = g_bc + ((size_t)b * LSEQ + l0) * 4;
        for (int i = tid; i < CHUNK*4; i += 256) bc_s[i] = bcg[i];
    }
    const float a0L = -__expf(A_log[2*d+0]) * LOG2E;
    const float a1L = -__expf(A_log[2*d+1]) * LOG2E;
    const float Dp  = D_param[d];
    const int sub = ch * 2 + half;
    const int ls  = half * 48;
    const size_t base = (((size_t)b*NSUBB + sub)*CDIM + d)*DSTATE;
    float h0 = g_hinit[base+0];
    float h1 = g_hinit[base+1];

    const size_t off = ((size_t)b * LSEQ + l0 + ls) * CDIM + d;
    const float* dtp = g_dt    + off;
    const float* xip = g_xi    + off;
    const float* zp  = g_zsilu + off;
    float*       yp  = g_y     + off;
    __syncthreads();

#pragma unroll 4
    for (int i = 0; i < 48; i++) {
        float dt = dtp[(size_t)i*CDIM];
        float xi = xip[(size_t)i*CDIM];
        float zv = zp [(size_t)i*CDIM];
        const int l = ls + i;
        float e0 = exp2f(dt * a0L);
        float e1 = exp2f(dt * a1L);
        float dbx = dt * xi;
        h0 = fmaf(e0, h0, dbx * bc_s[l*4+0]);
        h1 = fmaf(e1, h1, dbx * bc_s[l*4+1]);
        float y = fmaf(h0, bc_s[l*4+2], fmaf(h1, bc_s[l*4+3], Dp * xi));
        yp[(size_t)i*CDIM] = y * zv;
    }
}

// ---------------------------------------------------------------------------
// K5: out_proj + fused LayerNorm. Grid (72, 16).
// ---------------------------------------------------------------------------
__global__ __launch_bounds__(256)
void k_outproj_mma(const float* __restrict__ gamma, const float* __restrict__ beta,
                   float* __restrict__ out) {
    extern __shared__ __align__(16) char smraw[];
    const uint32_t sb = smem_u32(smraw);
    const int tid  = threadIdx.x;
    const int lane = tid & 31;
    const int wid  = tid >> 5;
    const int wm   = wid >> 2;
    const int wn   = wid & 3;
    const int b    = blockIdx.y;
    const int l0   = blockIdx.x * 128;

    {
        const float* yb = g_y + ((size_t)b * LSEQ + l0) * CDIM;
        for (int idx = tid; idx < 128 * 32; idx += 256) {
            int l = idx >> 5, k4 = (idx & 31) * 4;
            float4 v = *reinterpret_cast<const float4*>(&yb[(size_t)l * CDIM + k4]);
            uint2 hi, lo; split_pack(v, hi, lo);
            uint32_t off = l * TPITCH_B + k4 * 2;
            *reinterpret_cast<uint2*>(smraw + SM_BH + off) = hi;
            *reinterpret_cast<uint2*>(smraw + SM_BL + off) = lo;
        }
    }
    __syncthreads();

    float acc[4][4][4];
    mma_tile_ga(acc, sb, g_waH + 2 * 2048, g_waL + 2 * 2048, lane, wm, wn);
    __syncthreads();

    float* tile = reinterpret_cast<float*>(smraw);   // [128][129]
    float* mu_s = tile + 128*129;
    float* rs_s = mu_s + 128;
#pragma unroll
    for (int mf = 0; mf < 4; mf++)
#pragma unroll
        for (int nf = 0; nf < 4; nf++) {
            int row = wm*64 + mf*16 + (lane >> 2);
            int col = wn*32 + nf*8 + (lane & 3) * 2;
            tile[ row      * 129 + col    ] = acc[mf][nf][0];
            tile[ row      * 129 + col + 1] = acc[mf][nf][1];
            tile[(row + 8) * 129 + col    ] = acc[mf][nf][2];
            tile[(row + 8) * 129 + col + 1] = acc[mf][nf][3];
        }
    __syncthreads();

    if (tid < 128) {
        float s = 0.f, q = 0.f;
#pragma unroll 8
        for (int o = 0; o < 128; o++) {
            float v = tile[o*129 + tid];
            s += v;
            q = fmaf(v, v, q);
        }
        float mu = s * (1.0f/128.0f);
        float var = q * (1.0f/128.0f) - mu*mu;
        mu_s[tid] = mu;
        rs_s[tid] = rsqrtf(var + 1e-5f);
    }
    __syncthreads();

    for (int p = tid; p < 128*32; p += 256) {
        int o  = p >> 5;
        int l4 = (p & 31) * 4;
        float g  = gamma[o];
        float bt = beta[o];
        float4 v;
        v.x = fmaf((tile[o*129 + l4+0] - mu_s[l4+0]) * rs_s[l4+0], g, bt);
        v.y = fmaf((tile[o*129 + l4+1] - mu_s[l4+1]) * rs_s[l4+1], g, bt);
        v.z = fmaf((tile[o*129 + l4+2] - mu_s[l4+2]) * rs_s[l4+2], g, bt);
        v.w = fmaf((tile[o*129 + l4+3] - mu_s[l4+3]) * rs_s[l4+3], g, bt);
        *reinterpret_cast<float4*>(&out[((size_t)(b*OUTC + o))*LSEQ + l0 + l4]) = v;
    }
}

// ---------------------------------------------------------------------------
extern "C" void kernel_launch(void* const* d_in, const int* in_sizes, int n_in,
                              void* d_out, int out_size) {
    const float* x          = (const float*)d_in[0];
    const float* in_proj_w  = (const float*)d_in[1];
    const float* conv_w     = (const float*)d_in[2];
    const float* conv_b     = (const float*)d_in[3];
    const float* x_proj_w   = (const float*)d_in[4];
    const float* dt_proj_w  = (const float*)d_in[5];
    const float* dt_proj_b  = (const float*)d_in[6];
    const float* A_log      = (const float*)d_in[7];
    const float* D_param    = (const float*)d_in[8];
    const float* out_proj_w = (const float*)d_in[9];
    const float* ln_gamma   = (const float*)d_in[10];
    const float* ln_beta    = (const float*)d_in[11];
    float* out = (float*)d_out;

    const int sm2 = SM2_FLOATS * sizeof(float);
    cudaFuncSetAttribute(k_prep,        cudaFuncAttributeMaxDynamicSharedMemorySize, (int)GEMM_SMEM);
    cudaFuncSetAttribute(k_inproj_mma,  cudaFuncAttributeMaxDynamicSharedMemorySize, (int)GEMM_SMEM);
    cudaFuncSetAttribute(k_phaseA,      cudaFuncAttributeMaxDynamicSharedMemorySize, sm2);
    cudaFuncSetAttribute(k_outproj_mma, cudaFuncAttributeMaxDynamicSharedMemorySize, (int)GEMM_SMEM);

    k_prep       <<<3, 256, GEMM_SMEM>>>(in_proj_w, out_proj_w);
    k_inproj_mma <<<dim3(LSEQ/128, 2, B_), 256, GEMM_SMEM>>>(x);
    k_phaseA     <<<dim3(NCHUNK, B_), 256, sm2>>>(conv_w, conv_b, x_proj_w,
                                                  dt_proj_w, dt_proj_b, A_log);
    k_comb1      <<<dim3(NGRP, B_), 256>>>();
    k_comb2      <<<B_, 256>>>();
    k_comb3      <<<dim3(NGRP, B_), 256>>>();
    k_scan       <<<dim3(NCHUNK, B_), 256>>>(A_log, D_param);
    k_outproj_mma<<<dim3(LSEQ/128, B_), 256, GEMM_SMEM>>>(ln_gamma, ln_beta, out);
}

// round 16
// speedup vs baseline: 1.4688x; 1.0036x over previous
#include <cuda_runtime.h>
#include <cuda_bf16.h>
#include <cstdint>
#include <math.h>

#define B_    16
#define CDIM  128
#define LSEQ  9216
#define DSTATE 2
#define DTRANK 8
#define OUTC  128
#define NPROJ 12
#define PCHUNK 128
#define NPTILE 72          // LSEQ/128
#define SUB   64
#define NSUBB 144          // 64-token subchunks per batch
#define NGRP  16           // groups of 9 subchunks
#define GSZ   9
#define LOG2E 1.4426950408889634f

// ---------------- device scratch ----------------
__device__ float g_xraw [(size_t)B_*LSEQ*CDIM];
__device__ float g_zsilu[(size_t)B_*LSEQ*CDIM];
__device__ float g_xi   [(size_t)B_*LSEQ*CDIM];
__device__ float g_dt   [(size_t)B_*LSEQ*CDIM];
__device__ float g_bc   [(size_t)B_*LSEQ*4];
__device__ float g_aggA [(size_t)B_*NSUBB*CDIM*DSTATE];
__device__ float g_aggH [(size_t)B_*NSUBB*CDIM*DSTATE];
__device__ float g_hinit[(size_t)B_*NSUBB*CDIM*DSTATE];
__device__ float g_grpA [(size_t)B_*NGRP*CDIM*DSTATE];
__device__ float g_grpH [(size_t)B_*NGRP*CDIM*DSTATE];
__device__ float g_ghin [(size_t)B_*NGRP*CDIM*DSTATE];
// pre-packed A fragments: [mat(3)][mtile(8)][ks(8)][lane(32)] uint4
__device__ uint4 g_waH[3*8*8*32];
__device__ uint4 g_waL[3*8*8*32];

__device__ __forceinline__ float silu_f(float v) {
    return __fdividef(v, 1.0f + __expf(-v));
}
__device__ __forceinline__ uint32_t smem_u32(const void* p) {
    uint32_t a;
    asm("{ .reg .u64 t; cvta.to.shared.u64 t, %1; cvt.u32.u64 %0, t; }" : "=r"(a) : "l"(p));
    return a;
}

#define LDMX4(r0,r1,r2,r3,addr) \
    asm volatile("ldmatrix.sync.aligned.m8n8.x4.shared.b16 {%0,%1,%2,%3}, [%4];" \
        : "=r"(r0),"=r"(r1),"=r"(r2),"=r"(r3) : "r"(addr))
#define MMA_BF16(D, A, B) \
    asm volatile("mma.sync.aligned.m16n8k16.row.col.f32.bf16.bf16.f32 " \
        "{%0,%1,%2,%3}, {%4,%5,%6,%7}, {%8,%9}, {%0,%1,%2,%3};" \
        : "+f"((D)[0]), "+f"((D)[1]), "+f"((D)[2]), "+f"((D)[3]) \
        : "r"((A)[0]), "r"((A)[1]), "r"((A)[2]), "r"((A)[3]), "r"((B)[0]), "r"((B)[1]))

__device__ __forceinline__ void split_pack(float4 v, uint2& hi, uint2& lo) {
    __nv_bfloat162 h0 = __floats2bfloat162_rn(v.x, v.y);
    __nv_bfloat162 h1 = __floats2bfloat162_rn(v.z, v.w);
    float r0 = v.x - __bfloat162float(h0.x);
    float r1 = v.y - __bfloat162float(h0.y);
    float r2 = v.z - __bfloat162float(h1.x);
    float r3 = v.w - __bfloat162float(h1.y);
    __nv_bfloat162 l0 = __floats2bfloat162_rn(r0, r1);
    __nv_bfloat162 l1 = __floats2bfloat162_rn(r2, r3);
    hi = make_uint2(*reinterpret_cast<uint32_t*>(&h0), *reinterpret_cast<uint32_t*>(&h1));
    lo = make_uint2(*reinterpret_cast<uint32_t*>(&l0), *reinterpret_cast<uint32_t*>(&l1));
}

// bf16 tile: [128 rows][128 k], pitch 272 B
#define TPITCH_B 272u
#define TILE_B   (128u*TPITCH_B)      // 34816
#define SM_BH    0u
#define SM_BL    34816u
#define GEMM_SMEM 69632u
#define SC_BC    69632u               // scanout: bc[128][4] f32
#define SCAN_SMEM (SC_BC + 2048u)     // 71680

// ---------------------------------------------------------------------------
// K0 prep: Wi (2 halves) + Wout -> bf16 hi/lo fragments in global.
// ---------------------------------------------------------------------------
__global__ __launch_bounds__(256)
void k_prep(const float* __restrict__ Wi, const float* __restrict__ Wout) {
    extern __shared__ __align__(16) char smraw[];
    const uint32_t sb = smem_u32(smraw);
    const int mat = blockIdx.x;
    const float* src = (mat == 2) ? Wout : (Wi + (size_t)mat * 128 * CDIM);
    const int tid = threadIdx.x, lane = tid & 31, wid = tid >> 5;

    for (int idx = tid; idx < 128 * 32; idx += 256) {
        int r = idx >> 5, k4 = (idx & 31) * 4;
        float4 w = *reinterpret_cast<const float4*>(&src[(size_t)r * CDIM + k4]);
        uint2 hi, lo; split_pack(w, hi, lo);
        uint32_t off = r * TPITCH_B + k4 * 2;
        *reinterpret_cast<uint2*>(smraw + SM_BH + off) = hi;
        *reinterpret_cast<uint2*>(smraw + SM_BL + off) = lo;
    }
    __syncthreads();

    const uint32_t a_off = (uint32_t)((lane & 15) * TPITCH_B + ((lane >> 4) * 8) * 2);
#pragma unroll
    for (int ks = 0; ks < 8; ks++) {
        uint32_t off = (wid * 16) * TPITCH_B + ks * 32 + a_off;
        uint4 vh, vl;
        LDMX4(vh.x, vh.y, vh.z, vh.w, sb + SM_BH + off);
        LDMX4(vl.x, vl.y, vl.z, vl.w, sb + SM_BL + off);
        int gi = ((mat * 8 + wid) * 8 + ks) * 32 + lane;
        g_waH[gi] = vh;
        g_waL[gi] = vl;
    }
}

// ---------------------------------------------------------------------------
// 128x128x128 3-term hi/lo MMA tile, A fragments from global, B from smem.
// ---------------------------------------------------------------------------
__device__ __forceinline__ void mma_tile_ga(float (*d)[4][4], uint32_t sb,
        const uint4* __restrict__ gaH, const uint4* __restrict__ gaL,
        int lane, int wm, int wn) {
    const uint32_t b_off = (uint32_t)((((lane >> 4) & 1) * 8 + (lane & 7)) * TPITCH_B
                                      + (((lane >> 3) & 1) * 8) * 2);
#pragma unroll
    for (int i = 0; i < 4; i++)
#pragma unroll
        for (int j = 0; j < 4; j++)
#pragma unroll
            for (int q = 0; q < 4; q++) d[i][j][q] = 0.f;

#pragma unroll 1
    for (int ks = 0; ks < 8; ks++) {
        uint4 ah4[4], al4[4];
#pragma unroll
        for (int mf = 0; mf < 4; mf++) {
            int gi = ((wm * 4 + mf) * 8 + ks) * 32 + lane;
            ah4[mf] = gaH[gi];
            al4[mf] = gaL[gi];
        }
        const uint32_t kb = ks * 32;
        uint32_t bh[4][2], bl[4][2];
#pragma unroll
        for (int p = 0; p < 2; p++) {
            uint32_t off = (wn*32 + p*16) * TPITCH_B + kb + b_off;
            LDMX4(bh[2*p][0], bh[2*p][1], bh[2*p+1][0], bh[2*p+1][1], sb + SM_BH + off);
            LDMX4(bl[2*p][0], bl[2*p][1], bl[2*p+1][0], bl[2*p+1][1], sb + SM_BL + off);
        }
#pragma unroll
        for (int mf = 0; mf < 4; mf++) {
            const uint32_t* ah = reinterpret_cast<const uint32_t*>(&ah4[mf]);
            const uint32_t* al = reinterpret_cast<const uint32_t*>(&al4[mf]);
#pragma unroll
            for (int nf = 0; nf < 4; nf++) {
                MMA_BF16(d[mf][nf], ah, bh[nf]);
                MMA_BF16(d[mf][nf], ah, bl[nf]);
                MMA_BF16(d[mf][nf], al, bh[nf]);
            }
        }
    }
}

// ---------------------------------------------------------------------------
// K1: in_proj. Grid (72, 2, 16).
// ---------------------------------------------------------------------------
__global__ __launch_bounds__(256)
void k_inproj_mma(const float* __restrict__ x) {
    extern __shared__ __align__(16) char smraw[];
    const uint32_t sb = smem_u32(smraw);
    const int tid  = threadIdx.x;
    const int lane = tid & 31;
    const int wid  = tid >> 5;
    const int wm   = wid >> 2;
    const int wn   = wid & 3;
    const int b    = blockIdx.z;
    const int half = blockIdx.y;
    const int l0   = blockIdx.x * 128;

    {
        const float* xb = x + (size_t)b * CDIM * LSEQ;
        for (int idx = tid; idx < 128 * 32; idx += 256) {
            int k = idx >> 5, l4 = (idx & 31) * 4;
            float4 v = *reinterpret_cast<const float4*>(&xb[(size_t)k * LSEQ + l0 + l4]);
            float vv[4] = {v.x, v.y, v.z, v.w};
#pragma unroll
            for (int i = 0; i < 4; i++) {
                __nv_bfloat16 h = __float2bfloat16(vv[i]);
                __nv_bfloat16 l = __float2bfloat16(vv[i] - __bfloat162float(h));
                uint32_t off = (l4 + i) * TPITCH_B + k * 2;
                *reinterpret_cast<__nv_bfloat16*>(smraw + SM_BH + off) = h;
                *reinterpret_cast<__nv_bfloat16*>(smraw + SM_BL + off) = l;
            }
        }
    }
    __syncthreads();

    float acc[4][4][4];
    mma_tile_ga(acc, sb, g_waH + half * 2048, g_waL + half * 2048, lane, wm, wn);
    __syncthreads();

    float* tile = reinterpret_cast<float*>(smraw);   // [128][129]
#pragma unroll
    for (int mf = 0; mf < 4; mf++)
#pragma unroll
        for (int nf = 0; nf < 4; nf++) {
            int row = wm*64 + mf*16 + (lane >> 2);
            int col = wn*32 + nf*8 + (lane & 3) * 2;
            tile[ row      * 129 + col    ] = acc[mf][nf][0];
            tile[ row      * 129 + col + 1] = acc[mf][nf][1];
            tile[(row + 8) * 129 + col    ] = acc[mf][nf][2];
            tile[(row + 8) * 129 + col + 1] = acc[mf][nf][3];
        }
    __syncthreads();

    float* dst = (half == 0 ? g_xraw : g_zsilu);
    for (int idx = tid; idx < 128 * 32; idx += 256) {
        int l = idx >> 5, e4 = (idx & 31) * 4;
        float4 v;
        v.x = tile[(e4+0)*129 + l];
        v.y = tile[(e4+1)*129 + l];
        v.z = tile[(e4+2)*129 + l];
        v.w = tile[(e4+3)*129 + l];
        if (half == 1) { v.x = silu_f(v.x); v.y = silu_f(v.y); v.z = silu_f(v.z); v.w = silu_f(v.w); }
        *reinterpret_cast<float4*>(&dst[((size_t)b * LSEQ + l0 + l) * CDIM + e4]) = v;
    }
}

// ---------------------------------------------------------------------------
// K2: phaseA — 128-token tiles. conv+silu -> xi, x_dbl -> bc, dt + 64-token
// subchunk aggregates. Grid (NPTILE, B_), 256 threads.
// ---------------------------------------------------------------------------
#define SM2_FLOATS (128*132 + 12*132 + 128*16)   // 82112 B

__global__ __launch_bounds__(256)
void k_phaseA(const float* __restrict__ conv_w, const float* __restrict__ conv_b,
              const float* __restrict__ x_proj_w, const float* __restrict__ dt_proj_w,
              const float* __restrict__ dt_proj_b, const float* __restrict__ A_log) {
    extern __shared__ float sm[];
    float* xi_s = sm;                   // [128][132]
    float* xw_s = sm + 128*132;         // [12][132]
    float* xd_s = xw_s + 12*132;        // [128][16]

    const int ch = blockIdx.x;
    const int b  = blockIdx.y;
    const int l0 = ch * PCHUNK;
    const int tid = threadIdx.x;
    const int d    = tid & 127;
    const int half = tid >> 7;

    for (int i = tid; i < NPROJ*CDIM; i += 256)
        xw_s[(i >> 7)*132 + (i & 127)] = x_proj_w[i];

    {
        const float cw0 = conv_w[d*4+0], cw1 = conv_w[d*4+1];
        const float cw2 = conv_w[d*4+2], cw3 = conv_w[d*4+3];
        const float cb  = conv_b[d];
        const float* xr = g_xraw + (size_t)b * LSEQ * CDIM;
        float* xo = g_xi + ((size_t)b * LSEQ + l0) * CDIM + d;
        const int ls = half * SUB;
        const int la0 = l0 + ls;
        float p0 = (la0 >= 3) ? xr[(size_t)(la0-3)*CDIM + d] : 0.f;
        float p1 = (la0 >= 2) ? xr[(size_t)(la0-2)*CDIM + d] : 0.f;
        float p2 = (la0 >= 1) ? xr[(size_t)(la0-1)*CDIM + d] : 0.f;
#pragma unroll 4
        for (int l = ls; l < ls + SUB; l++) {
            float c = xr[(size_t)(l0+l)*CDIM + d];
            float a = fmaf(cw0,p0, fmaf(cw1,p1, fmaf(cw2,p2, fmaf(cw3,c, cb))));
            float v = silu_f(a);
            xi_s[l*132 + d] = v;
            xo[(size_t)l*CDIM] = v;
            p0 = p1; p1 = p2; p2 = c;
        }
    }
    __syncthreads();

    {
        float* bco = g_bc + ((size_t)b * LSEQ + l0) * 4;
        for (int p = tid; p < PCHUNK*NPROJ; p += 256) {
            int l = p / 12, j = p - l*12;
            const float4* xr4 = reinterpret_cast<const float4*>(&xi_s[l*132]);
            const float4* wr4 = reinterpret_cast<const float4*>(&xw_s[j*132]);
            float s = 0.f;
#pragma unroll
            for (int k = 0; k < 32; k++) {
                float4 xa = xr4[k], wa = wr4[k];
                s = fmaf(xa.x, wa.x, s); s = fmaf(xa.y, wa.y, s);
                s = fmaf(xa.z, wa.z, s); s = fmaf(xa.w, wa.w, s);
            }
            xd_s[l*16 + j] = s;
            if (j >= 8) bco[l*4 + (j-8)] = s;
        }
    }
    __syncthreads();

    // dt + 64-token subchunk aggregates: thread (d, half)
    {
        float wdt[DTRANK];
#pragma unroll
        for (int r = 0; r < DTRANK; r++) wdt[r] = dt_proj_w[d*DTRANK + r];
        const float bdt = dt_proj_b[d];
        const float a0L = -__expf(A_log[2*d+0]) * LOG2E;
        const float a1L = -__expf(A_log[2*d+1]) * LOG2E;
        const int ls = half * SUB;
        float* dto = g_dt + ((size_t)b * LSEQ + l0 + ls) * CDIM + d;

        float h0 = 0.f, h1 = 0.f, sdt = 0.f;
#pragma unroll 2
        for (int i = 0; i < SUB; i++) {
            const float* xd = &xd_s[(ls + i)*16];
            float t = bdt;
#pragma unroll
            for (int r = 0; r < DTRANK; r++) t = fmaf(xd[r], wdt[r], t);
            float ex = __expf(t);
            float dt = (t > 20.f) ? t : __logf(1.f + ex);
            dto[(size_t)i*CDIM] = dt;
            sdt += dt;
            float e0 = exp2f(dt * a0L);
            float e1 = exp2f(dt * a1L);
            float dbx = dt * xi_s[(ls + i)*132 + d];
            h0 = fmaf(e0, h0, dbx * xd[8]);
            h1 = fmaf(e1, h1, dbx * xd[9]);
        }
        const int sub = ch * 2 + half;
        const size_t base = (((size_t)b*NSUBB + sub)*CDIM + d)*DSTATE;
        g_aggA[base+0] = exp2f(a0L * sdt);
        g_aggA[base+1] = exp2f(a1L * sdt);
        g_aggH[base+0] = h0;
        g_aggH[base+1] = h1;
    }
}

// ---------------------------------------------------------------------------
// K3 a/b/c: two-level combine over 144 subchunks = 16 groups x 9.
// ---------------------------------------------------------------------------
__global__ __launch_bounds__(256)
void k_comb1() {    // per-group aggregate. grid (NGRP, B_)
    const int g = blockIdx.x, b = blockIdx.y, rem = threadIdx.x;
    float A0 = 1.f, h = 0.f;
#pragma unroll
    for (int i = 0; i < GSZ; i++) {
        const size_t idx = (((size_t)b*NSUBB + g*GSZ + i) * CDIM * DSTATE) + rem;
        float a = g_aggA[idx];
        h = fmaf(a, h, g_aggH[idx]);
        A0 *= a;
    }
    const size_t o = (((size_t)b*NGRP + g) * CDIM * DSTATE) + rem;
    g_grpA[o] = A0;
    g_grpH[o] = h;
}

__global__ __launch_bounds__(256)
void k_comb2() {    // chain groups. grid (B_)
    const int b = blockIdx.x, rem = threadIdx.x;
    float h = 0.f;
#pragma unroll
    for (int g = 0; g < NGRP; g++) {
        const size_t o = (((size_t)b*NGRP + g) * CDIM * DSTATE) + rem;
        g_ghin[o] = h;
        h = fmaf(g_grpA[o], h, g_grpH[o]);
    }
}

__global__ __launch_bounds__(256)
void k_comb3() {    // within-group entries. grid (NGRP, B_)
    const int g = blockIdx.x, b = blockIdx.y, rem = threadIdx.x;
    float h = g_ghin[(((size_t)b*NGRP + g) * CDIM * DSTATE) + rem];
#pragma unroll
    for (int i = 0; i < GSZ; i++) {
        const size_t idx = (((size_t)b*NSUBB + g*GSZ + i) * CDIM * DSTATE) + rem;
        g_hinit[idx] = h;
        h = fmaf(g_aggA[idx], h, g_aggH[idx]);
    }
}

// ---------------------------------------------------------------------------
// K4: scanout — scan (y -> bf16 hi/lo smem operands) + out_proj MMA + LN.
// Grid (NPTILE, B_), 256 threads. smem 71680 B.
// ---------------------------------------------------------------------------
__global__ __launch_bounds__(256)
void k_scanout(const float* __restrict__ A_log, const float* __restrict__ D_param,
               const float* __restrict__ gamma, const float* __restrict__ beta,
               float* __restrict__ out) {
    extern __shared__ __align__(16) char smraw[];
    const uint32_t sb = smem_u32(smraw);
    const int tid  = threadIdx.x;
    const int lane = tid & 31;
    const int wid  = tid >> 5;
    const int wm   = wid >> 2;
    const int wn   = wid & 3;
    const int b    = blockIdx.y;
    const int l0   = blockIdx.x * 128;

    // bc tile
    {
        float4* bc4 = reinterpret_cast<float4*>(smraw + SC_BC);
        const float4* bcg = reinterpret_cast<const float4*>(g_bc + ((size_t)b*LSEQ + l0)*4);
        for (int i = tid; i < 128; i += 256) bc4[i] = bcg[i];
    }
    __syncthreads();

    // scan: thread (d, half) over 64-token subchunk, y -> BH/BL
    {
        const int d    = tid & 127;
        const int half = tid >> 7;
        const int sub  = blockIdx.x * 2 + half;
        const int ls   = half * SUB;
        const float* bc_s = reinterpret_cast<const float*>(smraw + SC_BC);
        const float a0L = -__expf(A_log[2*d+0]) * LOG2E;
        const float a1L = -__expf(A_log[2*d+1]) * LOG2E;
        const float Dp  = D_param[d];
        const size_t hb = (((size_t)b*NSUBB + sub)*CDIM + d)*DSTATE;
        float h0 = g_hinit[hb+0];
        float h1 = g_hinit[hb+1];
        const size_t off = ((size_t)b * LSEQ + l0 + ls) * CDIM + d;
        const float* dtp = g_dt    + off;
        const float* xip = g_xi    + off;
        const float* zp  = g_zsilu + off;
#pragma unroll 4
        for (int i = 0; i < SUB; i++) {
            float dt = dtp[(size_t)i*CDIM];
            float xi = xip[(size_t)i*CDIM];
            float zv = zp [(size_t)i*CDIM];
            const int l = ls + i;
            float e0 = exp2f(dt * a0L);
            float e1 = exp2f(dt * a1L);
            float dbx = dt * xi;
            h0 = fmaf(e0, h0, dbx * bc_s[l*4+0]);
            h1 = fmaf(e1, h1, dbx * bc_s[l*4+1]);
            float y = fmaf(h0, bc_s[l*4+2], fmaf(h1, bc_s[l*4+3], Dp * xi));
            y *= zv;
            __nv_bfloat16 yh = __float2bfloat16(y);
            __nv_bfloat16 yl = __float2bfloat16(y - __bfloat162float(yh));
            uint32_t so = l * TPITCH_B + d * 2;
            *reinterpret_cast<__nv_bfloat16*>(smraw + SM_BH + so) = yh;
            *reinterpret_cast<__nv_bfloat16*>(smraw + SM_BL + so) = yl;
        }
    }
    __syncthreads();

    float acc[4][4][4];
    mma_tile_ga(acc, sb, g_waH + 2 * 2048, g_waL + 2 * 2048, lane, wm, wn);
    __syncthreads();

    // stage D[o][l] (pitch 129), LN over o, coalesced write
    float* tile = reinterpret_cast<float*>(smraw);   // [128][129]
    float* mu_s = tile + 128*129;
    float* rs_s = mu_s + 128;
#pragma unroll
    for (int mf = 0; mf < 4; mf++)
#pragma unroll
        for (int nf = 0; nf < 4; nf++) {
            int row = wm*64 + mf*16 + (lane >> 2);
            int col = wn*32 + nf*8 + (lane & 3) * 2;
            tile[ row      * 129 + col    ] = acc[mf][nf][0];
            tile[ row      * 129 + col + 1] = acc[mf][nf][1];
            tile[(row + 8) * 129 + col    ] = acc[mf][nf][2];
            tile[(row + 8) * 129 + col + 1] = acc[mf][nf][3];
        }
    __syncthreads();

    if (tid < 128) {
        float s = 0.f, q = 0.f;
#pragma unroll 8
        for (int o = 0; o < 128; o++) {
            float v = tile[o*129 + tid];
            s += v;
            q = fmaf(v, v, q);
        }
        float mu = s * (1.0f/128.0f);
        float var = q * (1.0f/128.0f) - mu*mu;
        mu_s[tid] = mu;
        rs_s[tid] = rsqrtf(var + 1e-5f);
    }
    __syncthreads();

    for (int p = tid; p < 128*32; p += 256) {
        int o  = p >> 5;
        int l4 = (p & 31) * 4;
        float g  = gamma[o];
        float bt = beta[o];
        float4 v;
        v.x = fmaf((tile[o*129 + l4+0] - mu_s[l4+0]) * rs_s[l4+0], g, bt);
        v.y = fmaf((tile[o*129 + l4+1] - mu_s[l4+1]) * rs_s[l4+1], g, bt);
        v.z = fmaf((tile[o*129 + l4+2] - mu_s[l4+2]) * rs_s[l4+2], g, bt);
        v.w = fmaf((tile[o*129 + l4+3] - mu_s[l4+3]) * rs_s[l4+3], g, bt);
        *reinterpret_cast<float4*>(&out[((size_t)(b*OUTC + o))*LSEQ + l0 + l4]) = v;
    }
}

// ---------------------------------------------------------------------------
extern "C" void kernel_launch(void* const* d_in, const int* in_sizes, int n_in,
                              void* d_out, int out_size) {
    const float* x          = (const float*)d_in[0];
    const float* in_proj_w  = (const float*)d_in[1];
    const float* conv_w     = (const float*)d_in[2];
    const float* conv_b     = (const float*)d_in[3];
    const float* x_proj_w   = (const float*)d_in[4];
    const float* dt_proj_w  = (const float*)d_in[5];
    const float* dt_proj_b  = (const float*)d_in[6];
    const float* A_log      = (const float*)d_in[7];
    const float* D_param    = (const float*)d_in[8];
    const float* out_proj_w = (const float*)d_in[9];
    const float* ln_gamma   = (const float*)d_in[10];
    const float* ln_beta    = (const float*)d_in[11];
    float* out = (float*)d_out;

    const int sm2 = SM2_FLOATS * sizeof(float);
    cudaFuncSetAttribute(k_prep,       cudaFuncAttributeMaxDynamicSharedMemorySize, (int)GEMM_SMEM);
    cudaFuncSetAttribute(k_inproj_mma, cudaFuncAttributeMaxDynamicSharedMemorySize, (int)GEMM_SMEM);
    cudaFuncSetAttribute(k_phaseA,     cudaFuncAttributeMaxDynamicSharedMemorySize, sm2);
    cudaFuncSetAttribute(k_scanout,    cudaFuncAttributeMaxDynamicSharedMemorySize, (int)SCAN_SMEM);

    k_prep      <<<3, 256, GEMM_SMEM>>>(in_proj_w, out_proj_w);
    k_inproj_mma<<<dim3(NPTILE, 2, B_), 256, GEMM_SMEM>>>(x);
    k_phaseA    <<<dim3(NPTILE, B_), 256, sm2>>>(conv_w, conv_b, x_proj_w,
                                                 dt_proj_w, dt_proj_b, A_log);
    k_comb1     <<<dim3(NGRP, B_), 256>>>();
    k_comb2     <<<B_, 256>>>();
    k_comb3     <<<dim3(NGRP, B_), 256>>>();
    k_scanout   <<<dim3(NPTILE, B_), 256, SCAN_SMEM>>>(A_log, D_param,
                                                       ln_gamma, ln_beta, out);
}

// round 17
// speedup vs baseline: 1.5326x; 1.0435x over previous
#include <cuda_runtime.h>
#include <cuda_bf16.h>
#include <cstdint>
#include <math.h>

#define B_    16
#define CDIM  128
#define LSEQ  9216
#define DSTATE 2
#define DTRANK 8
#define OUTC  128
#define NPROJ 12
#define NPTILE 72          // LSEQ/128
#define SUB   64
#define NSUBB 144          // 64-token subchunks per batch
#define NGRP  16           // groups of 9 subchunks
#define GSZ   9
#define LOG2E 1.4426950408889634f

// ---------------- device scratch ----------------
__device__ float g_zsilu[(size_t)B_*LSEQ*CDIM];
__device__ float g_xi   [(size_t)B_*LSEQ*CDIM];
__device__ float g_dt   [(size_t)B_*LSEQ*CDIM];
__device__ float g_bc   [(size_t)B_*LSEQ*4];
__device__ float g_aggA [(size_t)B_*NSUBB*CDIM*DSTATE];
__device__ float g_aggH [(size_t)B_*NSUBB*CDIM*DSTATE];
__device__ float g_hinit[(size_t)B_*NSUBB*CDIM*DSTATE];
__device__ float g_grpA [(size_t)B_*NGRP*CDIM*DSTATE];
__device__ float g_grpH [(size_t)B_*NGRP*CDIM*DSTATE];
__device__ float g_ghin [(size_t)B_*NGRP*CDIM*DSTATE];
// pre-packed A fragments: [mat(3)][mtile(8)][ks(8)][lane(32)] uint4
// mat0 = Wi rows 0..127 (x-half), mat1 = Wi rows 128..255 (z-half), mat2 = Wout
__device__ uint4 g_waH[3*8*8*32];
__device__ uint4 g_waL[3*8*8*32];

__device__ __forceinline__ float silu_f(float v) {
    return __fdividef(v, 1.0f + __expf(-v));
}
__device__ __forceinline__ uint32_t smem_u32(const void* p) {
    uint32_t a;
    asm("{ .reg .u64 t; cvta.to.shared.u64 t, %1; cvt.u32.u64 %0, t; }" : "=r"(a) : "l"(p));
    return a;
}

#define LDMX4(r0,r1,r2,r3,addr) \
    asm volatile("ldmatrix.sync.aligned.m8n8.x4.shared.b16 {%0,%1,%2,%3}, [%4];" \
        : "=r"(r0),"=r"(r1),"=r"(r2),"=r"(r3) : "r"(addr))
#define MMA_BF16(D, A, B) \
    asm volatile("mma.sync.aligned.m16n8k16.row.col.f32.bf16.bf16.f32 " \
        "{%0,%1,%2,%3}, {%4,%5,%6,%7}, {%8,%9}, {%0,%1,%2,%3};" \
        : "+f"((D)[0]), "+f"((D)[1]), "+f"((D)[2]), "+f"((D)[3]) \
        : "r"((A)[0]), "r"((A)[1]), "r"((A)[2]), "r"((A)[3]), "r"((B)[0]), "r"((B)[1]))

__device__ __forceinline__ void split_pack(float4 v, uint2& hi, uint2& lo) {
    __nv_bfloat162 h0 = __floats2bfloat162_rn(v.x, v.y);
    __nv_bfloat162 h1 = __floats2bfloat162_rn(v.z, v.w);
    float r0 = v.x - __bfloat162float(h0.x);
    float r1 = v.y - __bfloat162float(h0.y);
    float r2 = v.z - __bfloat162float(h1.x);
    float r3 = v.w - __bfloat162float(h1.y);
    __nv_bfloat162 l0 = __floats2bfloat162_rn(r0, r1);
    __nv_bfloat162 l1 = __floats2bfloat162_rn(r2, r3);
    hi = make_uint2(*reinterpret_cast<uint32_t*>(&h0), *reinterpret_cast<uint32_t*>(&h1));
    lo = make_uint2(*reinterpret_cast<uint32_t*>(&l0), *reinterpret_cast<uint32_t*>(&l1));
}

// bf16 tile: [128 rows][128 k], pitch 272 B
#define TPITCH_B 272u
#define TILE_B   (128u*TPITCH_B)      // 34816
#define SM_BH    0u
#define SM_BL    34816u
#define GEMM_SMEM 69632u
#define SC_BC    69632u               // scanout: bc[128][4] f32
#define SCAN_SMEM (SC_BC + 2048u)     // 71680

// fused K1 smem map (beyond BH/BL):
#define F_ZST  69632u                 // f32 zstage [128 l][68]  (34816 B)
#define F_XW   69632u                 // f32 [12][132] (after zstage done)
#define F_XD   75968u                 // f32 [128][16]
#define F_XH   104448u                // f32 [3][128] halo x cols
#define F_SMEM 105984u

// ---------------------------------------------------------------------------
// K0 prep: Wi (2 halves) + Wout -> bf16 hi/lo fragments in global.
// ---------------------------------------------------------------------------
__global__ __launch_bounds__(256)
void k_prep(const float* __restrict__ Wi, const float* __restrict__ Wout) {
    extern __shared__ __align__(16) char smraw[];
    const uint32_t sb = smem_u32(smraw);
    const int mat = blockIdx.x;
    const float* src = (mat == 2) ? Wout : (Wi + (size_t)mat * 128 * CDIM);
    const int tid = threadIdx.x, lane = tid & 31, wid = tid >> 5;

    for (int idx = tid; idx < 128 * 32; idx += 256) {
        int r = idx >> 5, k4 = (idx & 31) * 4;
        float4 w = *reinterpret_cast<const float4*>(&src[(size_t)r * CDIM + k4]);
        uint2 hi, lo; split_pack(w, hi, lo);
        uint32_t off = r * TPITCH_B + k4 * 2;
        *reinterpret_cast<uint2*>(smraw + SM_BH + off) = hi;
        *reinterpret_cast<uint2*>(smraw + SM_BL + off) = lo;
    }
    __syncthreads();

    const uint32_t a_off = (uint32_t)((lane & 15) * TPITCH_B + ((lane >> 4) * 8) * 2);
#pragma unroll
    for (int ks = 0; ks < 8; ks++) {
        uint32_t off = (wid * 16) * TPITCH_B + ks * 32 + a_off;
        uint4 vh, vl;
        LDMX4(vh.x, vh.y, vh.z, vh.w, sb + SM_BH + off);
        LDMX4(vl.x, vl.y, vl.z, vl.w, sb + SM_BL + off);
        int gi = ((mat * 8 + wid) * 8 + ks) * 32 + lane;
        g_waH[gi] = vh;
        g_waL[gi] = vl;
    }
}

// ---------------------------------------------------------------------------
// 128x128x128 3-term hi/lo MMA tile, A fragments from global, B from smem.
// ---------------------------------------------------------------------------
__device__ __forceinline__ void mma_tile_ga(float (*d)[4][4], uint32_t sb,
        const uint4* __restrict__ gaH, const uint4* __restrict__ gaL,
        int lane, int wm, int wn) {
    const uint32_t b_off = (uint32_t)((((lane >> 4) & 1) * 8 + (lane & 7)) * TPITCH_B
                                      + (((lane >> 3) & 1) * 8) * 2);
#pragma unroll
    for (int i = 0; i < 4; i++)
#pragma unroll
        for (int j = 0; j < 4; j++)
#pragma unroll
            for (int q = 0; q < 4; q++) d[i][j][q] = 0.f;

#pragma unroll 1
    for (int ks = 0; ks < 8; ks++) {
        uint4 ah4[4], al4[4];
#pragma unroll
        for (int mf = 0; mf < 4; mf++) {
            int gi = ((wm * 4 + mf) * 8 + ks) * 32 + lane;
            ah4[mf] = gaH[gi];
            al4[mf] = gaL[gi];
        }
        const uint32_t kb = ks * 32;
        uint32_t bh[4][2], bl[4][2];
#pragma unroll
        for (int p = 0; p < 2; p++) {
            uint32_t off = (wn*32 + p*16) * TPITCH_B + kb + b_off;
            LDMX4(bh[2*p][0], bh[2*p][1], bh[2*p+1][0], bh[2*p+1][1], sb + SM_BH + off);
            LDMX4(bl[2*p][0], bl[2*p][1], bl[2*p+1][0], bl[2*p+1][1], sb + SM_BL + off);
        }
#pragma unroll
        for (int mf = 0; mf < 4; mf++) {
            const uint32_t* ah = reinterpret_cast<const uint32_t*>(&ah4[mf]);
            const uint32_t* al = reinterpret_cast<const uint32_t*>(&al4[mf]);
#pragma unroll
            for (int nf = 0; nf < 4; nf++) {
                MMA_BF16(d[mf][nf], ah, bh[nf]);
                MMA_BF16(d[mf][nf], ah, bl[nf]);
                MMA_BF16(d[mf][nf], al, bh[nf]);
            }
        }
    }
}

// ---------------------------------------------------------------------------
// K1 fused: in_proj (both halves) + silu(z) + conv + x_proj + dt + aggregates.
// Grid (NPTILE, B_), 256 threads, smem 105984 B (occ 2).
// ---------------------------------------------------------------------------
__global__ __launch_bounds__(256)
void k_fused1(const float* __restrict__ x, const float* __restrict__ Wi,
              const float* __restrict__ conv_w, const float* __restrict__ conv_b,
              const float* __restrict__ x_proj_w, const float* __restrict__ dt_proj_w,
              const float* __restrict__ dt_proj_b, const float* __restrict__ A_log) {
    extern __shared__ __align__(16) char smraw[];
    const uint32_t sb = smem_u32(smraw);
    const int tid  = threadIdx.x;
    const int lane = tid & 31;
    const int wid  = tid >> 5;
    const int wm   = wid >> 2;
    const int wn   = wid & 3;
    const int b    = blockIdx.y;
    const int l0   = blockIdx.x * 128;

    // 1. x tile -> BH/BL operands; halo x cols -> F_XH
    {
        const float* xb = x + (size_t)b * CDIM * LSEQ;
        for (int idx = tid; idx < 128 * 32; idx += 256) {
            int k = idx >> 5, l4 = (idx & 31) * 4;
            float4 v = *reinterpret_cast<const float4*>(&xb[(size_t)k * LSEQ + l0 + l4]);
            float vv[4] = {v.x, v.y, v.z, v.w};
#pragma unroll
            for (int i = 0; i < 4; i++) {
                __nv_bfloat16 h = __float2bfloat16(vv[i]);
                __nv_bfloat16 l = __float2bfloat16(vv[i] - __bfloat162float(h));
                uint32_t off = (l4 + i) * TPITCH_B + k * 2;
                *reinterpret_cast<__nv_bfloat16*>(smraw + SM_BH + off) = h;
                *reinterpret_cast<__nv_bfloat16*>(smraw + SM_BL + off) = l;
            }
        }
        float* xh = reinterpret_cast<float*>(smraw + F_XH);
        for (int i = tid; i < 3 * 128; i += 256) {
            int j = i >> 7, k = i & 127;
            int lh = l0 - 3 + j;
            xh[i] = (lh >= 0) ? xb[(size_t)k * LSEQ + lh] : 0.f;
        }
    }
    __syncthreads();

    float acc[4][4][4];
    // 2. z-half MMA (Wi rows 128..255 = mat1)
    mma_tile_ga(acc, sb, g_waH + 2048, g_waL + 2048, lane, wm, wn);
    __syncthreads();

    // 3. z staging: 2 rounds of 64 e-rows through zstage [128 l][68]
    {
        float* zst = reinterpret_cast<float*>(smraw + F_ZST);
#pragma unroll
        for (int r = 0; r < 2; r++) {
            if (wm == r) {
#pragma unroll
                for (int mf = 0; mf < 4; mf++)
#pragma unroll
                    for (int nf = 0; nf < 4; nf++) {
                        int el  = mf*16 + (lane >> 2);
                        int col = wn*32 + nf*8 + (lane & 3) * 2;
                        zst[ col     *68 + el    ] = acc[mf][nf][0];
                        zst[(col + 1)*68 + el    ] = acc[mf][nf][1];
                        zst[ col     *68 + el + 8] = acc[mf][nf][2];
                        zst[(col + 1)*68 + el + 8] = acc[mf][nf][3];
                    }
            }
            __syncthreads();
            for (int idx = tid; idx < 128 * 16; idx += 256) {
                int l = idx >> 4, e4 = (idx & 15) * 4;
                float4 v = *reinterpret_cast<const float4*>(&zst[l*68 + e4]);
                v.x = silu_f(v.x); v.y = silu_f(v.y); v.z = silu_f(v.z); v.w = silu_f(v.w);
                *reinterpret_cast<float4*>(
                    &g_zsilu[((size_t)b*LSEQ + l0 + l)*CDIM + r*64 + e4]) = v;
            }
            __syncthreads();
        }
    }

    // 4. x-half MMA (Wi rows 0..127 = mat0)
    mma_tile_ga(acc, sb, g_waH, g_waL, lane, wm, wn);
    __syncthreads();   // BH/BL reads complete before xtile overwrite

    // 5. stage x fragments -> xtile rows 3..130; halo GEMV -> rows 0..2; xw load
    float* xtile = reinterpret_cast<float*>(smraw);     // [131][132] over BH/BL
#pragma unroll
    for (int mf = 0; mf < 4; mf++)
#pragma unroll
        for (int nf = 0; nf < 4; nf++) {
            int e   = wm*64 + mf*16 + (lane >> 2);
            int col = wn*32 + nf*8 + (lane & 3) * 2;
            xtile[(3 + col    )*132 + e    ] = acc[mf][nf][0];
            xtile[(3 + col + 1)*132 + e    ] = acc[mf][nf][1];
            xtile[(3 + col    )*132 + e + 8] = acc[mf][nf][2];
            xtile[(3 + col + 1)*132 + e + 8] = acc[mf][nf][3];
        }
    {
        const float* xh = reinterpret_cast<const float*>(smraw + F_XH);
        for (int t = tid; t < 3 * 128; t += 256) {
            int j = t >> 7, d2 = t & 127;
            const float* wr = &Wi[(size_t)d2 * CDIM];
            const float* xr = &xh[j * 128];
            float s = 0.f;
#pragma unroll 8
            for (int k = 0; k < CDIM; k++) s = fmaf(wr[k], xr[k], s);
            xtile[j * 132 + d2] = s;
        }
        float* xw = reinterpret_cast<float*>(smraw + F_XW);
        for (int i = tid; i < NPROJ*CDIM; i += 256)
            xw[(i >> 7)*132 + (i & 127)] = x_proj_w[i];
    }
    __syncthreads();

    // 6. conv + silu IN PLACE on xtile (pre-read p-init to avoid cross-half race)
    const int d    = tid & 127;
    const int half = tid >> 7;
    const int ls   = half * SUB;
    float p0 = xtile[(ls    )*132 + d];
    float p1 = xtile[(ls + 1)*132 + d];
    float p2 = xtile[(ls + 2)*132 + d];
    __syncthreads();
    {
        const float cw0 = conv_w[d*4+0], cw1 = conv_w[d*4+1];
        const float cw2 = conv_w[d*4+2], cw3 = conv_w[d*4+3];
        const float cb  = conv_b[d];
        float* xo = g_xi + ((size_t)b * LSEQ + l0 + ls) * CDIM + d;
#pragma unroll 4
        for (int i = 0; i < SUB; i++) {
            const int l = ls + i;
            float c = xtile[(l + 3)*132 + d];
            float a = fmaf(cw0,p0, fmaf(cw1,p1, fmaf(cw2,p2, fmaf(cw3,c, cb))));
            float v = silu_f(a);
            xtile[(l + 3)*132 + d] = v;
            xo[(size_t)i*CDIM] = v;
            p0 = p1; p1 = p2; p2 = c;
        }
    }
    __syncthreads();

    // 7. x_proj: 128 tokens x 12 dots (xi in xtile rows 3..130)
    {
        const float* xw = reinterpret_cast<const float*>(smraw + F_XW);
        float* xd_s = reinterpret_cast<float*>(smraw + F_XD);
        float* bco = g_bc + ((size_t)b * LSEQ + l0) * 4;
        for (int p = tid; p < 128*NPROJ; p += 256) {
            int l = p / 12, j = p - l*12;
            const float4* xr4 = reinterpret_cast<const float4*>(&xtile[(l + 3)*132]);
            const float4* wr4 = reinterpret_cast<const float4*>(&xw[j*132]);
            float s = 0.f;
#pragma unroll
            for (int k = 0; k < 32; k++) {
                float4 xa = xr4[k], wa = wr4[k];
                s = fmaf(xa.x, wa.x, s); s = fmaf(xa.y, wa.y, s);
                s = fmaf(xa.z, wa.z, s); s = fmaf(xa.w, wa.w, s);
            }
            xd_s[l*16 + j] = s;
            if (j >= 8) bco[l*4 + (j-8)] = s;
        }
    }
    __syncthreads();

    // 8. dt + 64-token subchunk aggregates: thread (d, half)
    {
        const float* xd_s = reinterpret_cast<const float*>(smraw + F_XD);
        float wdt[DTRANK];
#pragma unroll
        for (int r = 0; r < DTRANK; r++) wdt[r] = dt_proj_w[d*DTRANK + r];
        const float bdt = dt_proj_b[d];
        const float a0L = -__expf(A_log[2*d+0]) * LOG2E;
        const float a1L = -__expf(A_log[2*d+1]) * LOG2E;
        float* dto = g_dt + ((size_t)b * LSEQ + l0 + ls) * CDIM + d;

        float h0 = 0.f, h1 = 0.f, sdt = 0.f;
#pragma unroll 2
        for (int i = 0; i < SUB; i++) {
            const float* xd = &xd_s[(ls + i)*16];
            float t = bdt;
#pragma unroll
            for (int r = 0; r < DTRANK; r++) t = fmaf(xd[r], wdt[r], t);
            float ex = __expf(t);
            float dt = (t > 20.f) ? t : __logf(1.f + ex);
            dto[(size_t)i*CDIM] = dt;
            sdt += dt;
            float e0 = exp2f(dt * a0L);
            float e1 = exp2f(dt * a1L);
            float dbx = dt * xtile[(ls + i + 3)*132 + d];
            h0 = fmaf(e0, h0, dbx * xd[8]);
            h1 = fmaf(e1, h1, dbx * xd[9]);
        }
        const int sub = blockIdx.x * 2 + half;
        const size_t base = (((size_t)b*NSUBB + sub)*CDIM + d)*DSTATE;
        g_aggA[base+0] = exp2f(a0L * sdt);
        g_aggA[base+1] = exp2f(a1L * sdt);
        g_aggH[base+0] = h0;
        g_aggH[base+1] = h1;
    }
}

// ---------------------------------------------------------------------------
// K3 a/b/c: two-level combine over 144 subchunks = 16 groups x 9.
// ---------------------------------------------------------------------------
__global__ __launch_bounds__(256)
void k_comb1() {    // per-group aggregate. grid (NGRP, B_)
    const int g = blockIdx.x, b = blockIdx.y, rem = threadIdx.x;
    float A0 = 1.f, h = 0.f;
#pragma unroll
    for (int i = 0; i < GSZ; i++) {
        const size_t idx = (((size_t)b*NSUBB + g*GSZ + i) * CDIM * DSTATE) + rem;
        float a = g_aggA[idx];
        h = fmaf(a, h, g_aggH[idx]);
        A0 *= a;
    }
    const size_t o = (((size_t)b*NGRP + g) * CDIM * DSTATE) + rem;
    g_grpA[o] = A0;
    g_grpH[o] = h;
}

__global__ __launch_bounds__(256)
void k_comb2() {    // chain groups. grid (B_)
    const int b = blockIdx.x, rem = threadIdx.x;
    float h = 0.f;
#pragma unroll
    for (int g = 0; g < NGRP; g++) {
        const size_t o = (((size_t)b*NGRP + g) * CDIM * DSTATE) + rem;
        g_ghin[o] = h;
        h = fmaf(g_grpA[o], h, g_grpH[o]);
    }
}

__global__ __launch_bounds__(256)
void k_comb3() {    // within-group entries. grid (NGRP, B_)
    const int g = blockIdx.x, b = blockIdx.y, rem = threadIdx.x;
    float h = g_ghin[(((size_t)b*NGRP + g) * CDIM * DSTATE) + rem];
#pragma unroll
    for (int i = 0; i < GSZ; i++) {
        const size_t idx = (((size_t)b*NSUBB + g*GSZ + i) * CDIM * DSTATE) + rem;
        g_hinit[idx] = h;
        h = fmaf(g_aggA[idx], h, g_aggH[idx]);
    }
}

// ---------------------------------------------------------------------------
// K4: scanout — scan (y -> bf16 hi/lo smem operands) + out_proj MMA + LN.
// Grid (NPTILE, B_), 256 threads.
// ---------------------------------------------------------------------------
__global__ __launch_bounds__(256)
void k_scanout(const float* __restrict__ A_log, const float* __restrict__ D_param,
               const float* __restrict__ gamma, const float* __restrict__ beta,
               float* __restrict__ out) {
    extern __shared__ __align__(16) char smraw[];
    const uint32_t sb = smem_u32(smraw);
    const int tid  = threadIdx.x;
    const int lane = tid & 31;
    const int wid  = tid >> 5;
    const int wm   = wid >> 2;
    const int wn   = wid & 3;
    const int b    = blockIdx.y;
    const int l0   = blockIdx.x * 128;

    // bc tile
    {
        float4* bc4 = reinterpret_cast<float4*>(smraw + SC_BC);
        const float4* bcg = reinterpret_cast<const float4*>(g_bc + ((size_t)b*LSEQ + l0)*4);
        for (int i = tid; i < 128; i += 256) bc4[i] = bcg[i];
    }
    __syncthreads();

    // scan: thread (d, half) over 64-token subchunk, y -> BH/BL
    {
        const int d    = tid & 127;
        const int half = tid >> 7;
        const int sub  = blockIdx.x * 2 + half;
        const int ls   = half * SUB;
        const float* bc_s = reinterpret_cast<const float*>(smraw + SC_BC);
        const float a0L = -__expf(A_log[2*d+0]) * LOG2E;
        const float a1L = -__expf(A_log[2*d+1]) * LOG2E;
        const float Dp  = D_param[d];
        const size_t hb = (((size_t)b*NSUBB + sub)*CDIM + d)*DSTATE;
        float h0 = g_hinit[hb+0];
        float h1 = g_hinit[hb+1];
        const size_t off = ((size_t)b * LSEQ + l0 + ls) * CDIM + d;
        const float* dtp = g_dt    + off;
        const float* xip = g_xi    + off;
        const float* zp  = g_zsilu + off;
#pragma unroll 4
        for (int i = 0; i < SUB; i++) {
            float dt = dtp[(size_t)i*CDIM];
            float xi = xip[(size_t)i*CDIM];
            float zv = zp [(size_t)i*CDIM];
            const int l = ls + i;
            float e0 = exp2f(dt * a0L);
            float e1 = exp2f(dt * a1L);
            float dbx = dt * xi;
            h0 = fmaf(e0, h0, dbx * bc_s[l*4+0]);
            h1 = fmaf(e1, h1, dbx * bc_s[l*4+1]);
            float y = fmaf(h0, bc_s[l*4+2], fmaf(h1, bc_s[l*4+3], Dp * xi));
            y *= zv;
            __nv_bfloat16 yh = __float2bfloat16(y);
            __nv_bfloat16 yl = __float2bfloat16(y - __bfloat162float(yh));
            uint32_t so = l * TPITCH_B + d * 2;
            *reinterpret_cast<__nv_bfloat16*>(smraw + SM_BH + so) = yh;
            *reinterpret_cast<__nv_bfloat16*>(smraw + SM_BL + so) = yl;
        }
    }
    __syncthreads();

    float acc[4][4][4];
    mma_tile_ga(acc, sb, g_waH + 2 * 2048, g_waL + 2 * 2048, lane, wm, wn);
    __syncthreads();

    // stage D[o][l] (pitch 129), LN over o, coalesced write
    float* tile = reinterpret_cast<float*>(smraw);   // [128][129]
    float* mu_s = tile + 128*129;
    float* rs_s = mu_s + 128;
#pragma unroll
    for (int mf = 0; mf < 4; mf++)
#pragma unroll
        for (int nf = 0; nf < 4; nf++) {
            int row = wm*64 + mf*16 + (lane >> 2);
            int col = wn*32 + nf*8 + (lane & 3) * 2;
            tile[ row      * 129 + col    ] = acc[mf][nf][0];
            tile[ row      * 129 + col + 1] = acc[mf][nf][1];
            tile[(row + 8) * 129 + col    ] = acc[mf][nf][2];
            tile[(row + 8) * 129 + col + 1] = acc[mf][nf][3];
        }
    __syncthreads();

    if (tid < 128) {
        float s = 0.f, q = 0.f;
#pragma unroll 8
        for (int o = 0; o < 128; o++) {
            float v = tile[o*129 + tid];
            s += v;
            q = fmaf(v, v, q);
        }
        float mu = s * (1.0f/128.0f);
        float var = q * (1.0f/128.0f) - mu*mu;
        mu_s[tid] = mu;
        rs_s[tid] = rsqrtf(var + 1e-5f);
    }
    __syncthreads();

    for (int p = tid; p < 128*32; p += 256) {
        int o  = p >> 5;
        int l4 = (p & 31) * 4;
        float g  = gamma[o];
        float bt = beta[o];
        float4 v;
        v.x = fmaf((tile[o*129 + l4+0] - mu_s[l4+0]) * rs_s[l4+0], g, bt);
        v.y = fmaf((tile[o*129 + l4+1] - mu_s[l4+1]) * rs_s[l4+1], g, bt);
        v.z = fmaf((tile[o*129 + l4+2] - mu_s[l4+2]) * rs_s[l4+2], g, bt);
        v.w = fmaf((tile[o*129 + l4+3] - mu_s[l4+3]) * rs_s[l4+3], g, bt);
        *reinterpret_cast<float4*>(&out[((size_t)(b*OUTC + o))*LSEQ + l0 + l4]) = v;
    }
}

// ---------------------------------------------------------------------------
extern "C" void kernel_launch(void* const* d_in, const int* in_sizes, int n_in,
                              void* d_out, int out_size) {
    const float* x          = (const float*)d_in[0];
    const float* in_proj_w  = (const float*)d_in[1];
    const float* conv_w     = (const float*)d_in[2];
    const float* conv_b     = (const float*)d_in[3];
    const float* x_proj_w   = (const float*)d_in[4];
    const float* dt_proj_w  = (const float*)d_in[5];
    const float* dt_proj_b  = (const float*)d_in[6];
    const float* A_log      = (const float*)d_in[7];
    const float* D_param    = (const float*)d_in[8];
    const float* out_proj_w = (const float*)d_in[9];
    const float* ln_gamma   = (const float*)d_in[10];
    const float* ln_beta    = (const float*)d_in[11];
    float* out = (float*)d_out;

    cudaFuncSetAttribute(k_prep,    cudaFuncAttributeMaxDynamicSharedMemorySize, (int)GEMM_SMEM);
    cudaFuncSetAttribute(k_fused1,  cudaFuncAttributeMaxDynamicSharedMemorySize, (int)F_SMEM);
    cudaFuncSetAttribute(k_scanout, cudaFuncAttributeMaxDynamicSharedMemorySize, (int)SCAN_SMEM);

    k_prep   <<<3, 256, GEMM_SMEM>>>(in_proj_w, out_proj_w);
    k_fused1 <<<dim3(NPTILE, B_), 256, F_SMEM>>>(x, in_proj_w, conv_w, conv_b,
                                                 x_proj_w, dt_proj_w, dt_proj_b, A_log);
    k_comb1  <<<dim3(NGRP, B_), 256>>>();
    k_comb2  <<<B_, 256>>>();
    k_comb3  <<<dim3(NGRP, B_), 256>>>();
    k_scanout<<<dim3(NPTILE, B_), 256, SCAN_SMEM>>>(A_log, D_param,
                                                    ln_gamma, ln_beta, out);
}